// round 11
// baseline (speedup 1.0000x reference)
#include <cuda_runtime.h>
#include <cuda_bf16.h>
#include <cuda_fp16.h>

#define NCLUST 256
#define NPT    128
#define NEDGE  1024
#define VS     32
#define VOXN   (VS*VS*VS)   // 32768

typedef unsigned long long ull;

__device__ __forceinline__ ull pk2(float lo, float hi) {
    ull r; asm("mov.b64 %0, {%1,%2};" : "=l"(r) : "f"(lo), "f"(hi)); return r;
}
__device__ __forceinline__ void fma2(ull& d, ull a, ull b) {
    asm("fma.rn.f32x2 %0, %1, %2, %0;" : "+l"(d) : "l"(a), "l"(b));
}
__device__ __forceinline__ float2 upk2(ull v) {
    float2 r; asm("mov.b64 {%0,%1}, %2;" : "=f"(r.x), "=f"(r.y) : "l"(v)); return r;
}
__device__ __forceinline__ unsigned smem_u32(const void* p) {
    unsigned a;
    asm("{ .reg .u64 t; cvta.to.shared.u64 t, %1; cvt.u32.u64 %0, t; }" : "=r"(a) : "l"(p));
    return a;
}

// Scratch (device globals)
__device__ float  g_cvox[NCLUST * VOXN];             // 32 MB
__device__ float  g_c1c[NCLUST * 4096 * 16];         // 67 MB, layout [c][sp][ic]
__device__ float  g_c2[NEDGE * 32 * 512];            // 67 MB, layout [e][oc][sp]
__device__ float  g_w3t[32 * 27 * 64];               // W3 -> [ic][tap][oc]
__device__ __align__(16) __half g_w2h[32 * 448];     // W2 fp16 [oc][tap*16+ic], K pad 448
__device__ int    g_eidx_is_i64;
__device__ int    g_mask_is_u8;

// ---------------------------------------------------------------------------
// Kernel D: dtype layout detection
// ---------------------------------------------------------------------------
__global__ void detect_kernel(const int* __restrict__ eidx_w,
                              const unsigned int* __restrict__ mask_w,
                              int E, int maskWords)
{
    __shared__ int oddNZ, bigW;
    if (threadIdx.x == 0) { oddNZ = 0; bigW = 0; }
    __syncthreads();
    for (int i = threadIdx.x; i < E; i += blockDim.x)
        if (eidx_w[2 * i + 1] != 0) atomicOr(&oddNZ, 1);
    for (int i = threadIdx.x; i < maskWords; i += blockDim.x)
        if (mask_w[i] > 1u) atomicOr(&bigW, 1);
    __syncthreads();
    if (threadIdx.x == 0) {
        g_eidx_is_i64 = (oddNZ == 0) ? 1 : 0;
        g_mask_is_u8  = bigW;
    }
}

// ---------------------------------------------------------------------------
// Kernel W: W3 -> [ic][tap][oc] fp32; W2 -> fp16 [oc][448]
// ---------------------------------------------------------------------------
__global__ void wtrans_kernel(const float* __restrict__ W2,
                              const float* __restrict__ W3)
{
    int i = blockIdx.x * blockDim.x + threadIdx.x;
    if (i < 64 * 32 * 27) {
        int oc = i / (32 * 27), r = i % (32 * 27), ic = r / 27, tap = r % 27;
        g_w3t[(ic * 27 + tap) * 64 + oc] = W3[i];
    }
    if (i < 32 * 448) {
        int oc = i / 448, k = i % 448;
        float v = 0.0f;
        if (k < 432) {
            int tap = k >> 4, ic = k & 15;
            v = W2[(oc * 16 + ic) * 27 + tap];
        }
        g_w2h[i] = __float2half(v);
    }
}

// ---------------------------------------------------------------------------
// Kernel 0: per-cluster voxelization (ovx/ovy/ovz tables, dynamic smem)
// ---------------------------------------------------------------------------
#define VOX_SMEM ((3 * NPT * VS + 4 * NPT + 6 * NPT) * 4)   // 54272 B

__global__ __launch_bounds__(256) void vox_kernel(
    const float* __restrict__ data,
    const int* __restrict__ clusts,
    const void* __restrict__ cmask)
{
    extern __shared__ __align__(16) float dsmv[];
    float* ovy = dsmv;
    float* ovz = dsmv + NPT * VS;
    float* ovx = dsmv + 2 * NPT * VS;
    float* sw  = dsmv + 3 * NPT * VS;
    float* spx = sw  + NPT;
    float* spy = spx + NPT;
    float* spz = spy + NPT;
    float* red = spz + NPT;

    const int c = blockIdx.x;
    const int t = threadIdx.x;
    const int mask_u8 = g_mask_is_u8;

    if (t < NPT) {
        int idx = clusts[c * NPT + t];
        int m;
        if (mask_u8) m = ((const unsigned char*)cmask)[c * NPT + t];
        else         m = ((const int*)cmask)[c * NPT + t];
        float x = data[idx * 5 + 0];
        float y = data[idx * 5 + 1];
        float z = data[idx * 5 + 2];
        float v = data[idx * 5 + 4];
        spx[t] = x; spy[t] = y; spz[t] = z;
        sw[t]  = m ? v : 0.0f;
        red[0*NPT + t] = m ? x :  1e9f;
        red[1*NPT + t] = m ? y :  1e9f;
        red[2*NPT + t] = m ? z :  1e9f;
        red[3*NPT + t] = m ? x : -1e9f;
        red[4*NPT + t] = m ? y : -1e9f;
        red[5*NPT + t] = m ? z : -1e9f;
    }
    __syncthreads();
    for (int s = 64; s > 0; s >>= 1) {
        if (t < s) {
            red[0*NPT + t] = fminf(red[0*NPT + t], red[0*NPT + t + s]);
            red[1*NPT + t] = fminf(red[1*NPT + t], red[1*NPT + t + s]);
            red[2*NPT + t] = fminf(red[2*NPT + t], red[2*NPT + t + s]);
            red[3*NPT + t] = fmaxf(red[3*NPT + t], red[3*NPT + t + s]);
            red[4*NPT + t] = fmaxf(red[4*NPT + t], red[4*NPT + t + s]);
            red[5*NPT + t] = fmaxf(red[5*NPT + t], red[5*NPT + t + s]);
        }
        __syncthreads();
    }
    const float minx = red[0], miny = red[NPT], minz = red[2*NPT];
    const float rx = red[3*NPT] - minx;
    const float ry = red[4*NPT] - miny;
    const float rz = red[5*NPT] - minz;
    const float mr = fmaxf(rx, fmaxf(ry, rz)) + 1.0f;
    const float gs  = 1.0f / mr;
    const float rgs = mr;
    const float ns  = 1.0f / (float)VS;

    {
        int p    = t & (NPT - 1);
        int half = t >> 7;
        float vx = (spx[p] - minx - rx * 0.5f - 0.5f) * gs + 0.5f;
        float vy = (spy[p] - miny - ry * 0.5f - 0.5f) * gs + 0.5f;
        float vz = (spz[p] - minz - rz * 0.5f - 0.5f) * gs + 0.5f;
        for (int b = half * 16; b < half * 16 + 16; ++b) {
            float lo = (float)b * ns;
            float ox = fminf(vx + gs, lo + ns) - fmaxf(vx, lo);
            float oy = fminf(vy + gs, lo + ns) - fmaxf(vy, lo);
            float oz = fminf(vz + gs, lo + ns) - fmaxf(vz, lo);
            ovx[p * VS + b] = fmaxf(ox, 0.0f) * rgs;
            ovy[p * VS + b] = fmaxf(oy, 0.0f) * rgs;
            ovz[p * VS + b] = fmaxf(oz, 0.0f) * rgs;
        }
    }
    __syncthreads();

    float* outp = g_cvox + (size_t)c * VOXN;
    for (int pass = 0; pass < 4; ++pass) {
        int jk = t + pass * 256;
        int j = jk >> 5, k = jk & 31;
        float acc[VS];
#pragma unroll
        for (int i = 0; i < VS; ++i) acc[i] = 0.0f;
        for (int p = 0; p < NPT; ++p) {
            float ty = sw[p] * ovy[p * VS + j];
            if (ty != 0.0f) {
                float tz = ty * ovz[p * VS + k];
                const float4* ox4 = (const float4*)&ovx[p * VS];
#pragma unroll
                for (int i4 = 0; i4 < 8; ++i4) {
                    float4 o = ox4[i4];
                    acc[i4 * 4 + 0] += o.x * tz;
                    acc[i4 * 4 + 1] += o.y * tz;
                    acc[i4 * 4 + 2] += o.z * tz;
                    acc[i4 * 4 + 3] += o.w * tz;
                }
            }
        }
#pragma unroll
        for (int i = 0; i < VS; ++i)
            outp[i * (VS * VS) + jk] = acc[i];
    }
}

// ---------------------------------------------------------------------------
// Kernel 1: per-CLUSTER linear conv1, z-slab tiling. Output [sp][ic].
// ---------------------------------------------------------------------------
#define C1SD 36
#define C1PL (33 * C1SD)     // 1188
#define C1SZ (9 * C1PL)      // 10692 floats

__global__ __launch_bounds__(256, 2) void conv1c_kernel(
    const float* __restrict__ W1)
{
    __shared__ __align__(16) float s_in[C1SZ];
    __shared__ __align__(16) float s_w[27 * 16];

    const int c    = blockIdx.x >> 2;
    const int slab = blockIdx.x & 3;
    const int t = threadIdx.x;
    const float* __restrict__ A = g_cvox + (size_t)c * VOXN;

    for (int i = t; i < C1SZ; i += 256) s_in[i] = 0.0f;
    for (int i = t; i < 432; i += 256) {
        int oc = i / 27, tap = i % 27;
        s_w[tap * 16 + oc] = W1[i];
    }
    __syncthreads();

    const int z0 = slab * 8;
#pragma unroll
    for (int r = 0; r < 9; ++r) {
        int i4 = t + r * 256;
        int zz = i4 >> 8, j = i4 & 255;
        int gz = z0 + zz;
        if (gz < 32) {
            float4 v = *(const float4*)&A[gz * 1024 + j * 4];
            *(float4*)&s_in[zz * C1PL + (j >> 3) * C1SD + (j & 7) * 4] = v;
        }
    }
    __syncthreads();

    const int x = t & 15, y = t >> 4;

    ull acc[4][8];
#pragma unroll
    for (int q = 0; q < 4; ++q)
#pragma unroll
        for (int m = 0; m < 8; ++m) acc[q][m] = 0ULL;

#pragma unroll
    for (int dz = 0; dz < 3; ++dz)
#pragma unroll
        for (int dy = 0; dy < 3; ++dy) {
            float2 v01[4];
            float  v2s[4];
#pragma unroll
            for (int q = 0; q < 4; ++q) {
                const int o = (2 * q + dz) * C1PL + (2 * y + dy) * C1SD + 2 * x;
                v01[q] = *(const float2*)&s_in[o];
                v2s[q] = s_in[o + 2];
            }
#pragma unroll
            for (int dx = 0; dx < 3; ++dx) {
                const int tap = (dz * 3 + dy) * 3 + dx;
                const ulonglong2 w01 = *(const ulonglong2*)&s_w[tap * 16];
                const ulonglong2 w23 = *(const ulonglong2*)&s_w[tap * 16 + 4];
                const ulonglong2 w45 = *(const ulonglong2*)&s_w[tap * 16 + 8];
                const ulonglong2 w67 = *(const ulonglong2*)&s_w[tap * 16 + 12];
#pragma unroll
                for (int q = 0; q < 4; ++q) {
                    float v = (dx == 0) ? v01[q].x : (dx == 1) ? v01[q].y : v2s[q];
                    ull vv = pk2(v, v);
                    fma2(acc[q][0], vv, w01.x);
                    fma2(acc[q][1], vv, w01.y);
                    fma2(acc[q][2], vv, w23.x);
                    fma2(acc[q][3], vv, w23.y);
                    fma2(acc[q][4], vv, w45.x);
                    fma2(acc[q][5], vv, w45.y);
                    fma2(acc[q][6], vv, w67.x);
                    fma2(acc[q][7], vv, w67.y);
                }
            }
        }

    float* outp = g_c1c + (size_t)c * 4096 * 16;
#pragma unroll
    for (int q = 0; q < 4; ++q) {
        const int oz = slab * 4 + q;
        const int sp = oz * 256 + y * 16 + x;
        float vals[16];
#pragma unroll
        for (int m = 0; m < 8; ++m) {
            float2 p = upk2(acc[q][m]);
            vals[2 * m] = p.x; vals[2 * m + 1] = p.y;
        }
        float4* o4 = (float4*)(outp + sp * 16);
#pragma unroll
        for (int w = 0; w < 4; ++w) o4[w] = ((float4*)vals)[w];
    }
}

// ---------------------------------------------------------------------------
// Kernel 2: conv2 via mma.sync m16n8k16 (fp16 in, fp32 acc).
// 256 thr / 8 warps: warp = one m16-tile (zloc=w&1, ypair=w>>1) per z-pair tile.
// ---------------------------------------------------------------------------
#define C2_B_ROWB   912                        // 456 fp16 per oc row
#define C2_B_BYTES  (32 * C2_B_ROWB)           // 29184
#define C2_ACT_BYTES (5 * 17 * 18 * 48)        // 73440
#define C2_STAGE_F  (8 * 16 * 34)              // 4352 floats
#define C2MM_SMEM   (C2_B_BYTES + C2_ACT_BYTES + C2_STAGE_F * 4 + 64)

__global__ __launch_bounds__(256) void conv2_mma_kernel(
    const int* __restrict__ eidx,
    const float* __restrict__ b2,
    const float* __restrict__ b1,
    int E, int C)
{
    extern __shared__ __align__(16) char sm2[];
    char*  sB     = sm2;
    char*  sAct   = sm2 + C2_B_BYTES;
    float* sStage = (float*)(sm2 + C2_B_BYTES + C2_ACT_BYTES);
    float* sB1    = sStage + C2_STAGE_F;

    const int e = blockIdx.x;
    const int t = threadIdx.x;
    const int w = t >> 5, lane = t & 31;

    int ca, cb;
    if (g_eidx_is_i64) { ca = eidx[2 * e]; cb = eidx[2 * (E + e)]; }
    else               { ca = eidx[e];     cb = eidx[E + e];       }
    ca = min(max(ca, 0), C - 1);
    cb = min(max(cb, 0), C - 1);

    if (t < 16) sB1[t] = b1[t];

    // B fill: g_w2h [32][448] fp16 -> sB [32][456] rows (912B stride)
    {
        const unsigned* w2u = (const unsigned*)g_w2h;   // 32 x 224 u32
        for (int j = t; j < 32 * 224; j += 256) {
            int row = j / 224, ku = j % 224;
            *(unsigned*)(sB + row * C2_B_ROWB + ku * 4) = w2u[j];
        }
    }
    __syncthreads();

    const float4* __restrict__ A4 = (const float4*)(g_c1c + (size_t)ca * 65536);
    const float4* __restrict__ B4 = (const float4*)(g_c1c + (size_t)cb * 65536);
    const float4* b1q = (const float4*)sB1;

    // per-thread mma constants (identical fragment mapping to R10)
    const int xr   = lane & 7;
    const int ysel = (lane >> 3) & 1;
    const int hh   = (lane >> 4) & 1;
    const int zloc = w & 1, ypair = w >> 1;        // 8 warps -> 8 m16 tiles
    const unsigned actB = smem_u32(sAct);
    const unsigned bBs  = smem_u32(sB);
    const int bgrp = lane >> 3, brow = lane & 7;
    const unsigned bAddr0 = bBs + (unsigned)(((bgrp >> 1) * 8 + brow) * C2_B_ROWB
                                             + (bgrp & 1) * 16);
    float* stage = sStage + w * (16 * 34);
    float* outp = g_c2 + (size_t)e * 32 * 512;
    const float bias2 = __ldg(&b2[lane]);

    for (int t2 = 0; t2 < 4; ++t2) {
        // ---- act fill: 5 planes, channel-last fp16, relu(linA+linB+b1)
        for (int r = 0; r < 23; ++r) {
            int i = t + r * 256;
            if (i < 5780) {
                int icq = i & 3, v = i >> 2;
                int p = v / 289, rem = v % 289, yy = rem / 17, xx = rem % 17;
                int zz = t2 * 4 + p;
                uint2 st = make_uint2(0u, 0u);
                if (zz < 16 && yy < 16 && xx < 16) {
                    int gi = ((zz * 16 + yy) * 16 + xx) * 4 + icq;
                    float4 a = A4[gi], b = B4[gi], bb = b1q[icq];
                    __half2 h0 = __floats2half2_rn(fmaxf(a.x + b.x + bb.x, 0.0f),
                                                   fmaxf(a.y + b.y + bb.y, 0.0f));
                    __half2 h1 = __floats2half2_rn(fmaxf(a.z + b.z + bb.z, 0.0f),
                                                   fmaxf(a.w + b.w + bb.w, 0.0f));
                    st.x = *(unsigned*)&h0;
                    st.y = *(unsigned*)&h1;
                }
                int voff = ((p * 17 + yy) * 18 + (xx & 1) * 9 + (xx >> 1)) * 48 + icq * 8;
                *(uint2*)(sAct + voff) = st;
            }
        }
        __syncthreads();

        float acc[16];
#pragma unroll
        for (int q = 0; q < 16; ++q) acc[q] = 0.0f;

#pragma unroll
        for (int dz = 0; dz < 3; ++dz)
#pragma unroll
            for (int dy = 0; dy < 3; ++dy)
#pragma unroll
                for (int dx = 0; dx < 3; ++dx) {
                    const int g = (dz * 3 + dy) * 3 + dx;
                    unsigned bf[8];
                    {
                        unsigned a0 = bAddr0 + (unsigned)(g * 32);
                        asm volatile(
                            "ldmatrix.sync.aligned.m8n8.x4.shared.b16 {%0,%1,%2,%3}, [%4];"
                            : "=r"(bf[0]), "=r"(bf[1]), "=r"(bf[2]), "=r"(bf[3])
                            : "r"(a0));
                        asm volatile(
                            "ldmatrix.sync.aligned.m8n8.x4.shared.b16 {%0,%1,%2,%3}, [%4];"
                            : "=r"(bf[4]), "=r"(bf[5]), "=r"(bf[6]), "=r"(bf[7])
                            : "r"(a0 + 16u * C2_B_ROWB));
                    }
                    const int p = 2 * zloc + dz;
                    const int parity = dx & 1;
                    const int xh = xr + (dx >> 1);
                    const int yv = 4 * ypair + 2 * ysel + dy;
                    unsigned aAddr = actB
                        + (unsigned)(((p * 17 + yv) * 18 + parity * 9 + xh) * 48
                                     + hh * 16);
                    unsigned af[4];
                    asm volatile(
                        "ldmatrix.sync.aligned.m8n8.x4.shared.b16 {%0,%1,%2,%3}, [%4];"
                        : "=r"(af[0]), "=r"(af[1]), "=r"(af[2]), "=r"(af[3])
                        : "r"(aAddr));
#pragma unroll
                    for (int nt = 0; nt < 4; ++nt) {
                        float* c = &acc[nt * 4];
                        asm volatile(
                            "mma.sync.aligned.m16n8k16.row.col.f32.f16.f16.f32 "
                            "{%0,%1,%2,%3}, {%4,%5,%6,%7}, {%8,%9}, {%0,%1,%2,%3};"
                            : "+f"(c[0]), "+f"(c[1]), "+f"(c[2]), "+f"(c[3])
                            : "r"(af[0]), "r"(af[1]), "r"(af[2]), "r"(af[3]),
                              "r"(bf[nt * 2]), "r"(bf[nt * 2 + 1]));
                    }
                }

        // ---- epilogue: stage -> coalesced STG with bias+relu
        {
            const int row = lane >> 2, col2 = (lane & 3) * 2;
#pragma unroll
            for (int nt = 0; nt < 4; ++nt) {
                const int cb0 = nt * 8 + col2;
                *(float2*)&stage[row * 34 + cb0]       =
                    make_float2(acc[nt * 4 + 0], acc[nt * 4 + 1]);
                *(float2*)&stage[(row + 8) * 34 + cb0] =
                    make_float2(acc[nt * 4 + 2], acc[nt * 4 + 3]);
            }
            __syncwarp();
            {
                const int z = t2 * 2 + zloc;
                const int spb = z * 64 + ypair * 16;
                float o[16];
#pragma unroll
                for (int sp = 0; sp < 16; ++sp)
                    o[sp] = fmaxf(stage[sp * 34 + lane] + bias2, 0.0f);
                float4* dst = (float4*)&outp[lane * 512 + spb];
#pragma unroll
                for (int q = 0; q < 4; ++q) dst[q] = ((float4*)o)[q];
            }
            __syncwarp();
        }
        __syncthreads();
    }
}

// ---------------------------------------------------------------------------
// Kernel 3: conv3 (32->64ch) + relu + mean-pool + FC (fp32 FFMA2)
// ---------------------------------------------------------------------------
#define C3S1 12
#define C3S2 108
#define C3SZ (9*C3S2)      // 972

__global__ __launch_bounds__(256, 3) void conv3_kernel(
    const float* __restrict__ b3,
    const float* __restrict__ Wfc,
    const float* __restrict__ bfc,
    float* __restrict__ out)
{
    __shared__ __align__(16) float s_in[2][C3SZ];
    __shared__ __align__(16) float s_w[2][27 * 64];
    __shared__ __align__(16) float s_pool[64 * 65];
    __shared__ __align__(16) float s_pooled[64];

    const int e = blockIdx.x;
    const int t = threadIdx.x;
    const int og = t >> 6;
    const int s  = t & 63;
    const int lx = s & 3, ly = (s >> 2) & 3, lz = s >> 4;

    for (int i = t; i < 2 * C3SZ; i += 256) ((float*)s_in)[i] = 0.0f;

    ull acc[8];
#pragma unroll
    for (int m = 0; m < 8; ++m) acc[m] = 0ULL;

    const float4* __restrict__ src4 = (const float4*)(g_c2 + (size_t)e * 32 * 512);

    for (int ics = 0; ics < 32; ics += 2) {
        __syncthreads();
        {
            int buf = t >> 7, j = t & 127;
            float4 v = src4[(ics + buf) * 128 + j];
            int i = j * 4;
            int x = i & 7, y = (i >> 3) & 7, z = i >> 6;
            *(float4*)&s_in[buf][z * C3S2 + y * C3S1 + x] = v;
        }
        {
            const float4* wsrc = (const float4*)(g_w3t + ics * 1728);
            float4* wdst = (float4*)s_w;
#pragma unroll
            for (int r = 0; r < 4; ++r) {
                int i4 = t + r * 256;
                if (i4 < 864) wdst[i4] = wsrc[i4];
            }
        }
        __syncthreads();
#pragma unroll
        for (int buf = 0; buf < 2; ++buf) {
            const float* sin = s_in[buf];
            const float* sw  = s_w[buf];
#pragma unroll
            for (int dz = 0; dz < 3; ++dz)
#pragma unroll
                for (int dy = 0; dy < 3; ++dy) {
                    const int o = (2 * lz + dz) * C3S2 + (2 * ly + dy) * C3S1 + 2 * lx;
                    const float2 v01 = *(const float2*)&sin[o];
                    const float  v2s = sin[o + 2];
#pragma unroll
                    for (int dx = 0; dx < 3; ++dx) {
                        const int tap = (dz * 3 + dy) * 3 + dx;
                        const ulonglong2 w0 = *(const ulonglong2*)&sw[tap * 64 + og * 16];
                        const ulonglong2 w1 = *(const ulonglong2*)&sw[tap * 64 + og * 16 + 4];
                        const ulonglong2 w2 = *(const ulonglong2*)&sw[tap * 64 + og * 16 + 8];
                        const ulonglong2 w3 = *(const ulonglong2*)&sw[tap * 64 + og * 16 + 12];
                        float v = (dx == 0) ? v01.x : (dx == 1) ? v01.y : v2s;
                        ull vv = pk2(v, v);
                        fma2(acc[0], vv, w0.x);
                        fma2(acc[1], vv, w0.y);
                        fma2(acc[2], vv, w1.x);
                        fma2(acc[3], vv, w1.y);
                        fma2(acc[4], vv, w2.x);
                        fma2(acc[5], vv, w2.y);
                        fma2(acc[6], vv, w3.x);
                        fma2(acc[7], vv, w3.y);
                    }
                }
        }
    }
    __syncthreads();
#pragma unroll
    for (int m = 0; m < 8; ++m) {
        float2 p = upk2(acc[m]);
        const int oc0 = og * 16 + 2 * m;
        s_pool[s * 65 + oc0]     = fmaxf(p.x + __ldg(&b3[oc0]),     0.0f);
        s_pool[s * 65 + oc0 + 1] = fmaxf(p.y + __ldg(&b3[oc0 + 1]), 0.0f);
    }
    __syncthreads();
    if (t < 64) {
        float sum = 0.0f;
#pragma unroll 8
        for (int sp = 0; sp < 64; ++sp) sum += s_pool[sp * 65 + t];
        s_pooled[t] = sum * (1.0f / 64.0f);
    }
    __syncthreads();
    if (t < 64) {
        float r = bfc[t];
#pragma unroll 8
        for (int ic = 0; ic < 64; ++ic)
            r += s_pooled[ic] * __ldg(&Wfc[ic * 64 + t]);
        out[e * 64 + t] = r;
    }
}

// ---------------------------------------------------------------------------
extern "C" void kernel_launch(void* const* d_in, const int* in_sizes, int n_in,
                              void* d_out, int out_size)
{
    const float* data   = (const float*)d_in[0];
    const int*   clusts = (const int*)d_in[1];
    const void*  cmask  = d_in[2];
    const int*   eidx   = (const int*)d_in[3];
    const float* W1     = (const float*)d_in[4];
    const float* b1     = (const float*)d_in[5];
    const float* W2     = (const float*)d_in[6];
    const float* b2     = (const float*)d_in[7];
    const float* W3     = (const float*)d_in[8];
    const float* b3     = (const float*)d_in[9];
    const float* Wfc    = (const float*)d_in[10];
    const float* bfc    = (const float*)d_in[11];
    float*       out    = (float*)d_out;

    const int C = in_sizes[1] / NPT;   // 256
    const int E = in_sizes[3] / 2;     // 1024
    const int maskWords = in_sizes[2] / 4;

    cudaFuncSetAttribute(vox_kernel,
        cudaFuncAttributeMaxDynamicSharedMemorySize, VOX_SMEM);
    cudaFuncSetAttribute(conv2_mma_kernel,
        cudaFuncAttributeMaxDynamicSharedMemorySize, C2MM_SMEM);

    detect_kernel<<<1, 256>>>(eidx, (const unsigned int*)cmask, E, maskWords);
    wtrans_kernel<<<216, 256>>>(W2, W3);
    vox_kernel<<<C, 256, VOX_SMEM>>>(data, clusts, cmask);
    conv1c_kernel<<<C * 4, 256>>>(W1);
    conv2_mma_kernel<<<E, 256, C2MM_SMEM>>>(eidx, b2, b1, E, C);
    conv3_kernel<<<E, 256>>>(b3, Wfc, bfc, out);
}

// round 12
// speedup vs baseline: 1.2065x; 1.2065x over previous
#include <cuda_runtime.h>
#include <cuda_bf16.h>
#include <cuda_fp16.h>

#define NCLUST 256
#define NPT    128
#define NEDGE  1024
#define VS     32
#define VOXN   (VS*VS*VS)   // 32768

typedef unsigned long long ull;

__device__ __forceinline__ ull pk2(float lo, float hi) {
    ull r; asm("mov.b64 %0, {%1,%2};" : "=l"(r) : "f"(lo), "f"(hi)); return r;
}
__device__ __forceinline__ void fma2(ull& d, ull a, ull b) {
    asm("fma.rn.f32x2 %0, %1, %2, %0;" : "+l"(d) : "l"(a), "l"(b));
}
__device__ __forceinline__ float2 upk2(ull v) {
    float2 r; asm("mov.b64 {%0,%1}, %2;" : "=f"(r.x), "=f"(r.y) : "l"(v)); return r;
}
__device__ __forceinline__ unsigned smem_u32(const void* p) {
    unsigned a;
    asm("{ .reg .u64 t; cvta.to.shared.u64 t, %1; cvt.u32.u64 %0, t; }" : "=r"(a) : "l"(p));
    return a;
}

// Scratch (device globals)
__device__ float  g_cvox[NCLUST * VOXN];             // 32 MB
__device__ float  g_c1c[NCLUST * 4096 * 16];         // 67 MB, layout [c][sp][ic]
__device__ float  g_c2[NEDGE * 32 * 512];            // 67 MB, layout [e][oc][sp]
__device__ float  g_w3t[32 * 27 * 64];               // W3 -> [ic][tap][oc]
__device__ __align__(16) __half g_w2h[32 * 448];     // W2 fp16 [oc][tap*16+ic]
__device__ int    g_eidx_is_i64;
__device__ int    g_mask_is_u8;

// ---------------------------------------------------------------------------
// Kernel D: dtype layout detection
// ---------------------------------------------------------------------------
__global__ void detect_kernel(const int* __restrict__ eidx_w,
                              const unsigned int* __restrict__ mask_w,
                              int E, int maskWords)
{
    __shared__ int oddNZ, bigW;
    if (threadIdx.x == 0) { oddNZ = 0; bigW = 0; }
    __syncthreads();
    for (int i = threadIdx.x; i < E; i += blockDim.x)
        if (eidx_w[2 * i + 1] != 0) atomicOr(&oddNZ, 1);
    for (int i = threadIdx.x; i < maskWords; i += blockDim.x)
        if (mask_w[i] > 1u) atomicOr(&bigW, 1);
    __syncthreads();
    if (threadIdx.x == 0) {
        g_eidx_is_i64 = (oddNZ == 0) ? 1 : 0;
        g_mask_is_u8  = bigW;
    }
}

// ---------------------------------------------------------------------------
// Kernel W: W3 -> [ic][tap][oc] fp32; W2 -> fp16 [oc][448]
// ---------------------------------------------------------------------------
__global__ void wtrans_kernel(const float* __restrict__ W2,
                              const float* __restrict__ W3)
{
    int i = blockIdx.x * blockDim.x + threadIdx.x;
    if (i < 64 * 32 * 27) {
        int oc = i / (32 * 27), r = i % (32 * 27), ic = r / 27, tap = r % 27;
        g_w3t[(ic * 27 + tap) * 64 + oc] = W3[i];
    }
    if (i < 32 * 448) {
        int oc = i / 448, k = i % 448;
        float v = 0.0f;
        if (k < 432) {
            int tap = k >> 4, ic = k & 15;
            v = W2[(oc * 16 + ic) * 27 + tap];
        }
        g_w2h[i] = __float2half(v);
    }
}

// ---------------------------------------------------------------------------
// Kernel 0: per-cluster voxelization (ovx/ovy/ovz tables, dynamic smem)
// ---------------------------------------------------------------------------
#define VOX_SMEM ((3 * NPT * VS + 4 * NPT + 6 * NPT) * 4)   // 54272 B

__global__ __launch_bounds__(256) void vox_kernel(
    const float* __restrict__ data,
    const int* __restrict__ clusts,
    const void* __restrict__ cmask)
{
    extern __shared__ __align__(16) float dsmv[];
    float* ovy = dsmv;
    float* ovz = dsmv + NPT * VS;
    float* ovx = dsmv + 2 * NPT * VS;
    float* sw  = dsmv + 3 * NPT * VS;
    float* spx = sw  + NPT;
    float* spy = spx + NPT;
    float* spz = spy + NPT;
    float* red = spz + NPT;

    const int c = blockIdx.x;
    const int t = threadIdx.x;
    const int mask_u8 = g_mask_is_u8;

    if (t < NPT) {
        int idx = clusts[c * NPT + t];
        int m;
        if (mask_u8) m = ((const unsigned char*)cmask)[c * NPT + t];
        else         m = ((const int*)cmask)[c * NPT + t];
        float x = data[idx * 5 + 0];
        float y = data[idx * 5 + 1];
        float z = data[idx * 5 + 2];
        float v = data[idx * 5 + 4];
        spx[t] = x; spy[t] = y; spz[t] = z;
        sw[t]  = m ? v : 0.0f;
        red[0*NPT + t] = m ? x :  1e9f;
        red[1*NPT + t] = m ? y :  1e9f;
        red[2*NPT + t] = m ? z :  1e9f;
        red[3*NPT + t] = m ? x : -1e9f;
        red[4*NPT + t] = m ? y : -1e9f;
        red[5*NPT + t] = m ? z : -1e9f;
    }
    __syncthreads();
    for (int s = 64; s > 0; s >>= 1) {
        if (t < s) {
            red[0*NPT + t] = fminf(red[0*NPT + t], red[0*NPT + t + s]);
            red[1*NPT + t] = fminf(red[1*NPT + t], red[1*NPT + t + s]);
            red[2*NPT + t] = fminf(red[2*NPT + t], red[2*NPT + t + s]);
            red[3*NPT + t] = fmaxf(red[3*NPT + t], red[3*NPT + t + s]);
            red[4*NPT + t] = fmaxf(red[4*NPT + t], red[4*NPT + t + s]);
            red[5*NPT + t] = fmaxf(red[5*NPT + t], red[5*NPT + t + s]);
        }
        __syncthreads();
    }
    const float minx = red[0], miny = red[NPT], minz = red[2*NPT];
    const float rx = red[3*NPT] - minx;
    const float ry = red[4*NPT] - miny;
    const float rz = red[5*NPT] - minz;
    const float mr = fmaxf(rx, fmaxf(ry, rz)) + 1.0f;
    const float gs  = 1.0f / mr;
    const float rgs = mr;
    const float ns  = 1.0f / (float)VS;

    {
        int p    = t & (NPT - 1);
        int half = t >> 7;
        float vx = (spx[p] - minx - rx * 0.5f - 0.5f) * gs + 0.5f;
        float vy = (spy[p] - miny - ry * 0.5f - 0.5f) * gs + 0.5f;
        float vz = (spz[p] - minz - rz * 0.5f - 0.5f) * gs + 0.5f;
        for (int b = half * 16; b < half * 16 + 16; ++b) {
            float lo = (float)b * ns;
            float ox = fminf(vx + gs, lo + ns) - fmaxf(vx, lo);
            float oy = fminf(vy + gs, lo + ns) - fmaxf(vy, lo);
            float oz = fminf(vz + gs, lo + ns) - fmaxf(vz, lo);
            ovx[p * VS + b] = fmaxf(ox, 0.0f) * rgs;
            ovy[p * VS + b] = fmaxf(oy, 0.0f) * rgs;
            ovz[p * VS + b] = fmaxf(oz, 0.0f) * rgs;
        }
    }
    __syncthreads();

    float* outp = g_cvox + (size_t)c * VOXN;
    for (int pass = 0; pass < 4; ++pass) {
        int jk = t + pass * 256;
        int j = jk >> 5, k = jk & 31;
        float acc[VS];
#pragma unroll
        for (int i = 0; i < VS; ++i) acc[i] = 0.0f;
        for (int p = 0; p < NPT; ++p) {
            float ty = sw[p] * ovy[p * VS + j];
            if (ty != 0.0f) {
                float tz = ty * ovz[p * VS + k];
                const float4* ox4 = (const float4*)&ovx[p * VS];
#pragma unroll
                for (int i4 = 0; i4 < 8; ++i4) {
                    float4 o = ox4[i4];
                    acc[i4 * 4 + 0] += o.x * tz;
                    acc[i4 * 4 + 1] += o.y * tz;
                    acc[i4 * 4 + 2] += o.z * tz;
                    acc[i4 * 4 + 3] += o.w * tz;
                }
            }
        }
#pragma unroll
        for (int i = 0; i < VS; ++i)
            outp[i * (VS * VS) + jk] = acc[i];
    }
}

// ---------------------------------------------------------------------------
// Kernel 1: per-CLUSTER linear conv1, z-slab tiling. Output [sp][ic].
// ---------------------------------------------------------------------------
#define C1SD 36
#define C1PL (33 * C1SD)     // 1188
#define C1SZ (9 * C1PL)      // 10692 floats

__global__ __launch_bounds__(256, 2) void conv1c_kernel(
    const float* __restrict__ W1)
{
    __shared__ __align__(16) float s_in[C1SZ];
    __shared__ __align__(16) float s_w[27 * 16];

    const int c    = blockIdx.x >> 2;
    const int slab = blockIdx.x & 3;
    const int t = threadIdx.x;
    const float* __restrict__ A = g_cvox + (size_t)c * VOXN;

    for (int i = t; i < C1SZ; i += 256) s_in[i] = 0.0f;
    for (int i = t; i < 432; i += 256) {
        int oc = i / 27, tap = i % 27;
        s_w[tap * 16 + oc] = W1[i];
    }
    __syncthreads();

    const int z0 = slab * 8;
#pragma unroll
    for (int r = 0; r < 9; ++r) {
        int i4 = t + r * 256;
        int zz = i4 >> 8, j = i4 & 255;
        int gz = z0 + zz;
        if (gz < 32) {
            float4 v = *(const float4*)&A[gz * 1024 + j * 4];
            *(float4*)&s_in[zz * C1PL + (j >> 3) * C1SD + (j & 7) * 4] = v;
        }
    }
    __syncthreads();

    const int x = t & 15, y = t >> 4;

    ull acc[4][8];
#pragma unroll
    for (int q = 0; q < 4; ++q)
#pragma unroll
        for (int m = 0; m < 8; ++m) acc[q][m] = 0ULL;

#pragma unroll
    for (int dz = 0; dz < 3; ++dz)
#pragma unroll
        for (int dy = 0; dy < 3; ++dy) {
            float2 v01[4];
            float  v2s[4];
#pragma unroll
            for (int q = 0; q < 4; ++q) {
                const int o = (2 * q + dz) * C1PL + (2 * y + dy) * C1SD + 2 * x;
                v01[q] = *(const float2*)&s_in[o];
                v2s[q] = s_in[o + 2];
            }
#pragma unroll
            for (int dx = 0; dx < 3; ++dx) {
                const int tap = (dz * 3 + dy) * 3 + dx;
                const ulonglong2 w01 = *(const ulonglong2*)&s_w[tap * 16];
                const ulonglong2 w23 = *(const ulonglong2*)&s_w[tap * 16 + 4];
                const ulonglong2 w45 = *(const ulonglong2*)&s_w[tap * 16 + 8];
                const ulonglong2 w67 = *(const ulonglong2*)&s_w[tap * 16 + 12];
#pragma unroll
                for (int q = 0; q < 4; ++q) {
                    float v = (dx == 0) ? v01[q].x : (dx == 1) ? v01[q].y : v2s[q];
                    ull vv = pk2(v, v);
                    fma2(acc[q][0], vv, w01.x);
                    fma2(acc[q][1], vv, w01.y);
                    fma2(acc[q][2], vv, w23.x);
                    fma2(acc[q][3], vv, w23.y);
                    fma2(acc[q][4], vv, w45.x);
                    fma2(acc[q][5], vv, w45.y);
                    fma2(acc[q][6], vv, w67.x);
                    fma2(acc[q][7], vv, w67.y);
                }
            }
        }

    float* outp = g_c1c + (size_t)c * 4096 * 16;
#pragma unroll
    for (int q = 0; q < 4; ++q) {
        const int oz = slab * 4 + q;
        const int sp = oz * 256 + y * 16 + x;
        float vals[16];
#pragma unroll
        for (int m = 0; m < 8; ++m) {
            float2 p = upk2(acc[q][m]);
            vals[2 * m] = p.x; vals[2 * m + 1] = p.y;
        }
        float4* o4 = (float4*)(outp + sp * 16);
#pragma unroll
        for (int w = 0; w < 4; ++w) o4[w] = ((float4*)vals)[w];
    }
}

// ---------------------------------------------------------------------------
// Kernel 2: conv2 via mma.sync m16n8k16 (fp16 in, fp32 acc). 256 thr / 8 warps.
// Stage buffer ALIASED into act buffer -> smem 102.7 KB -> 2 CTAs/SM.
// ---------------------------------------------------------------------------
#define C2_B_ROWB   912                        // 456 fp16 per oc row
#define C2_B_BYTES  (32 * C2_B_ROWB)           // 29184
#define C2_ACT_BYTES (5 * 17 * 18 * 48)        // 73440
#define C2MM_SMEM   (C2_B_BYTES + C2_ACT_BYTES + 64)    // 102688 B

__global__ __launch_bounds__(256) void conv2_mma_kernel(
    const int* __restrict__ eidx,
    const float* __restrict__ b2,
    const float* __restrict__ b1,
    int E, int C)
{
    extern __shared__ __align__(16) char sm2[];
    char*  sB     = sm2;
    char*  sAct   = sm2 + C2_B_BYTES;
    float* sStage = (float*)sAct;               // ALIAS: act dead when staging
    float* sB1    = (float*)(sm2 + C2_B_BYTES + C2_ACT_BYTES);

    const int e = blockIdx.x;
    const int t = threadIdx.x;
    const int w = t >> 5, lane = t & 31;

    int ca, cb;
    if (g_eidx_is_i64) { ca = eidx[2 * e]; cb = eidx[2 * (E + e)]; }
    else               { ca = eidx[e];     cb = eidx[E + e];       }
    ca = min(max(ca, 0), C - 1);
    cb = min(max(cb, 0), C - 1);

    if (t < 16) sB1[t] = b1[t];

    // B fill: g_w2h [32][448] fp16 -> sB [32][456] rows (912B stride)
    {
        const unsigned* w2u = (const unsigned*)g_w2h;   // 32 x 224 u32
        for (int j = t; j < 32 * 224; j += 256) {
            int row = j / 224, ku = j % 224;
            *(unsigned*)(sB + row * C2_B_ROWB + ku * 4) = w2u[j];
        }
    }
    __syncthreads();

    const float4* __restrict__ A4 = (const float4*)(g_c1c + (size_t)ca * 65536);
    const float4* __restrict__ B4 = (const float4*)(g_c1c + (size_t)cb * 65536);
    const float4* b1q = (const float4*)sB1;

    const int xr   = lane & 7;
    const int ysel = (lane >> 3) & 1;
    const int hh   = (lane >> 4) & 1;
    const int zloc = w & 1, ypair = w >> 1;
    const unsigned actB = smem_u32(sAct);
    const unsigned bBs  = smem_u32(sB);
    const int bgrp = lane >> 3, brow = lane & 7;
    const unsigned bAddr0 = bBs + (unsigned)(((bgrp >> 1) * 8 + brow) * C2_B_ROWB
                                             + (bgrp & 1) * 16);
    float* stage = sStage + w * (16 * 34);
    float* outp = g_c2 + (size_t)e * 32 * 512;
    const float bias2 = __ldg(&b2[lane]);

    for (int t2 = 0; t2 < 4; ++t2) {
        // ---- act fill: 5 planes, channel-last fp16, relu(linA+linB+b1)
        for (int r = 0; r < 23; ++r) {
            int i = t + r * 256;
            if (i < 5780) {
                int icq = i & 3, v = i >> 2;
                int p = v / 289, rem = v % 289, yy = rem / 17, xx = rem % 17;
                int zz = t2 * 4 + p;
                uint2 st = make_uint2(0u, 0u);
                if (zz < 16 && yy < 16 && xx < 16) {
                    int gi = ((zz * 16 + yy) * 16 + xx) * 4 + icq;
                    float4 a = A4[gi], b = B4[gi], bb = b1q[icq];
                    __half2 h0 = __floats2half2_rn(fmaxf(a.x + b.x + bb.x, 0.0f),
                                                   fmaxf(a.y + b.y + bb.y, 0.0f));
                    __half2 h1 = __floats2half2_rn(fmaxf(a.z + b.z + bb.z, 0.0f),
                                                   fmaxf(a.w + b.w + bb.w, 0.0f));
                    st.x = *(unsigned*)&h0;
                    st.y = *(unsigned*)&h1;
                }
                int voff = ((p * 17 + yy) * 18 + (xx & 1) * 9 + (xx >> 1)) * 48 + icq * 8;
                *(uint2*)(sAct + voff) = st;
            }
        }
        __syncthreads();

        float acc[16];
#pragma unroll
        for (int q = 0; q < 16; ++q) acc[q] = 0.0f;

#pragma unroll
        for (int dz = 0; dz < 3; ++dz)
#pragma unroll
            for (int dy = 0; dy < 3; ++dy)
#pragma unroll
                for (int dx = 0; dx < 3; ++dx) {
                    const int g = (dz * 3 + dy) * 3 + dx;
                    unsigned bf[8];
                    {
                        unsigned a0 = bAddr0 + (unsigned)(g * 32);
                        asm volatile(
                            "ldmatrix.sync.aligned.m8n8.x4.shared.b16 {%0,%1,%2,%3}, [%4];"
                            : "=r"(bf[0]), "=r"(bf[1]), "=r"(bf[2]), "=r"(bf[3])
                            : "r"(a0));
                        asm volatile(
                            "ldmatrix.sync.aligned.m8n8.x4.shared.b16 {%0,%1,%2,%3}, [%4];"
                            : "=r"(bf[4]), "=r"(bf[5]), "=r"(bf[6]), "=r"(bf[7])
                            : "r"(a0 + 16u * C2_B_ROWB));
                    }
                    const int p = 2 * zloc + dz;
                    const int parity = dx & 1;
                    const int xh = xr + (dx >> 1);
                    const int yv = 4 * ypair + 2 * ysel + dy;
                    unsigned aAddr = actB
                        + (unsigned)(((p * 17 + yv) * 18 + parity * 9 + xh) * 48
                                     + hh * 16);
                    unsigned af[4];
                    asm volatile(
                        "ldmatrix.sync.aligned.m8n8.x4.shared.b16 {%0,%1,%2,%3}, [%4];"
                        : "=r"(af[0]), "=r"(af[1]), "=r"(af[2]), "=r"(af[3])
                        : "r"(aAddr));
#pragma unroll
                    for (int nt = 0; nt < 4; ++nt) {
                        float* c = &acc[nt * 4];
                        asm volatile(
                            "mma.sync.aligned.m16n8k16.row.col.f32.f16.f16.f32 "
                            "{%0,%1,%2,%3}, {%4,%5,%6,%7}, {%8,%9}, {%0,%1,%2,%3};"
                            : "+f"(c[0]), "+f"(c[1]), "+f"(c[2]), "+f"(c[3])
                            : "r"(af[0]), "r"(af[1]), "r"(af[2]), "r"(af[3]),
                              "r"(bf[nt * 2]), "r"(bf[nt * 2 + 1]));
                    }
                }

        // all warps done reading act for this tile -> safe to overwrite w/ stage
        __syncthreads();

        // ---- epilogue: stage -> coalesced STG with bias+relu
        {
            const int row = lane >> 2, col2 = (lane & 3) * 2;
#pragma unroll
            for (int nt = 0; nt < 4; ++nt) {
                const int cb0 = nt * 8 + col2;
                *(float2*)&stage[row * 34 + cb0]       =
                    make_float2(acc[nt * 4 + 0], acc[nt * 4 + 1]);
                *(float2*)&stage[(row + 8) * 34 + cb0] =
                    make_float2(acc[nt * 4 + 2], acc[nt * 4 + 3]);
            }
            __syncwarp();
            {
                const int z = t2 * 2 + zloc;
                const int spb = z * 64 + ypair * 16;
                float o[16];
#pragma unroll
                for (int sp = 0; sp < 16; ++sp)
                    o[sp] = fmaxf(stage[sp * 34 + lane] + bias2, 0.0f);
                float4* dst = (float4*)&outp[lane * 512 + spb];
#pragma unroll
                for (int q = 0; q < 4; ++q) dst[q] = ((float4*)o)[q];
            }
        }
        __syncthreads();
    }
}

// ---------------------------------------------------------------------------
// Kernel 3: conv3 (32->64ch) + relu + mean-pool + FC (fp32 FFMA2), 4 CTAs/SM
// ---------------------------------------------------------------------------
#define C3S1 12
#define C3S2 108
#define C3SZ (9*C3S2)      // 972

__global__ __launch_bounds__(256, 4) void conv3_kernel(
    const float* __restrict__ b3,
    const float* __restrict__ Wfc,
    const float* __restrict__ bfc,
    float* __restrict__ out)
{
    __shared__ __align__(16) float s_in[2][C3SZ];
    __shared__ __align__(16) float s_w[2][27 * 64];
    __shared__ __align__(16) float s_pool[64 * 65];
    __shared__ __align__(16) float s_pooled[64];

    const int e = blockIdx.x;
    const int t = threadIdx.x;
    const int og = t >> 6;
    const int s  = t & 63;
    const int lx = s & 3, ly = (s >> 2) & 3, lz = s >> 4;

    for (int i = t; i < 2 * C3SZ; i += 256) ((float*)s_in)[i] = 0.0f;

    ull acc[8];
#pragma unroll
    for (int m = 0; m < 8; ++m) acc[m] = 0ULL;

    const float4* __restrict__ src4 = (const float4*)(g_c2 + (size_t)e * 32 * 512);

    for (int ics = 0; ics < 32; ics += 2) {
        __syncthreads();
        {
            int buf = t >> 7, j = t & 127;
            float4 v = src4[(ics + buf) * 128 + j];
            int i = j * 4;
            int x = i & 7, y = (i >> 3) & 7, z = i >> 6;
            *(float4*)&s_in[buf][z * C3S2 + y * C3S1 + x] = v;
        }
        {
            const float4* wsrc = (const float4*)(g_w3t + ics * 1728);
            float4* wdst = (float4*)s_w;
#pragma unroll
            for (int r = 0; r < 4; ++r) {
                int i4 = t + r * 256;
                if (i4 < 864) wdst[i4] = wsrc[i4];
            }
        }
        __syncthreads();
#pragma unroll
        for (int buf = 0; buf < 2; ++buf) {
            const float* sin = s_in[buf];
            const float* sw  = s_w[buf];
#pragma unroll
            for (int dz = 0; dz < 3; ++dz)
#pragma unroll
                for (int dy = 0; dy < 3; ++dy) {
                    const int o = (2 * lz + dz) * C3S2 + (2 * ly + dy) * C3S1 + 2 * lx;
                    const float2 v01 = *(const float2*)&sin[o];
                    const float  v2s = sin[o + 2];
#pragma unroll
                    for (int dx = 0; dx < 3; ++dx) {
                        const int tap = (dz * 3 + dy) * 3 + dx;
                        const ulonglong2 w0 = *(const ulonglong2*)&sw[tap * 64 + og * 16];
                        const ulonglong2 w1 = *(const ulonglong2*)&sw[tap * 64 + og * 16 + 4];
                        const ulonglong2 w2 = *(const ulonglong2*)&sw[tap * 64 + og * 16 + 8];
                        const ulonglong2 w3 = *(const ulonglong2*)&sw[tap * 64 + og * 16 + 12];
                        float v = (dx == 0) ? v01.x : (dx == 1) ? v01.y : v2s;
                        ull vv = pk2(v, v);
                        fma2(acc[0], vv, w0.x);
                        fma2(acc[1], vv, w0.y);
                        fma2(acc[2], vv, w1.x);
                        fma2(acc[3], vv, w1.y);
                        fma2(acc[4], vv, w2.x);
                        fma2(acc[5], vv, w2.y);
                        fma2(acc[6], vv, w3.x);
                        fma2(acc[7], vv, w3.y);
                    }
                }
        }
    }
    __syncthreads();
#pragma unroll
    for (int m = 0; m < 8; ++m) {
        float2 p = upk2(acc[m]);
        const int oc0 = og * 16 + 2 * m;
        s_pool[s * 65 + oc0]     = fmaxf(p.x + __ldg(&b3[oc0]),     0.0f);
        s_pool[s * 65 + oc0 + 1] = fmaxf(p.y + __ldg(&b3[oc0 + 1]), 0.0f);
    }
    __syncthreads();
    if (t < 64) {
        float sum = 0.0f;
#pragma unroll 8
        for (int sp = 0; sp < 64; ++sp) sum += s_pool[sp * 65 + t];
        s_pooled[t] = sum * (1.0f / 64.0f);
    }
    __syncthreads();
    if (t < 64) {
        float r = bfc[t];
#pragma unroll 8
        for (int ic = 0; ic < 64; ++ic)
            r += s_pooled[ic] * __ldg(&Wfc[ic * 64 + t]);
        out[e * 64 + t] = r;
    }
}

// ---------------------------------------------------------------------------
extern "C" void kernel_launch(void* const* d_in, const int* in_sizes, int n_in,
                              void* d_out, int out_size)
{
    const float* data   = (const float*)d_in[0];
    const int*   clusts = (const int*)d_in[1];
    const void*  cmask  = d_in[2];
    const int*   eidx   = (const int*)d_in[3];
    const float* W1     = (const float*)d_in[4];
    const float* b1     = (const float*)d_in[5];
    const float* W2     = (const float*)d_in[6];
    const float* b2     = (const float*)d_in[7];
    const float* W3     = (const float*)d_in[8];
    const float* b3     = (const float*)d_in[9];
    const float* Wfc    = (const float*)d_in[10];
    const float* bfc    = (const float*)d_in[11];
    float*       out    = (float*)d_out;

    const int C = in_sizes[1] / NPT;   // 256
    const int E = in_sizes[3] / 2;     // 1024
    const int maskWords = in_sizes[2] / 4;

    cudaFuncSetAttribute(vox_kernel,
        cudaFuncAttributeMaxDynamicSharedMemorySize, VOX_SMEM);
    cudaFuncSetAttribute(conv2_mma_kernel,
        cudaFuncAttributeMaxDynamicSharedMemorySize, C2MM_SMEM);

    detect_kernel<<<1, 256>>>(eidx, (const unsigned int*)cmask, E, maskWords);
    wtrans_kernel<<<216, 256>>>(W2, W3);
    vox_kernel<<<C, 256, VOX_SMEM>>>(data, clusts, cmask);
    conv1c_kernel<<<C * 4, 256>>>(W1);
    conv2_mma_kernel<<<E, 256, C2MM_SMEM>>>(eidx, b2, b1, E, C);
    conv3_kernel<<<E, 256>>>(b3, Wfc, bfc, out);
}

// round 13
// speedup vs baseline: 1.6300x; 1.3510x over previous
#include <cuda_runtime.h>
#include <cuda_bf16.h>
#include <cuda_fp16.h>

#define NCLUST 256
#define NPT    128
#define NEDGE  1024
#define VS     32
#define VOXN   (VS*VS*VS)   // 32768

typedef unsigned long long ull;

__device__ __forceinline__ ull pk2(float lo, float hi) {
    ull r; asm("mov.b64 %0, {%1,%2};" : "=l"(r) : "f"(lo), "f"(hi)); return r;
}
__device__ __forceinline__ void fma2(ull& d, ull a, ull b) {
    asm("fma.rn.f32x2 %0, %1, %2, %0;" : "+l"(d) : "l"(a), "l"(b));
}
__device__ __forceinline__ float2 upk2(ull v) {
    float2 r; asm("mov.b64 {%0,%1}, %2;" : "=f"(r.x), "=f"(r.y) : "l"(v)); return r;
}
__device__ __forceinline__ unsigned smem_u32(const void* p) {
    unsigned a;
    asm("{ .reg .u64 t; cvta.to.shared.u64 t, %1; cvt.u32.u64 %0, t; }" : "=r"(a) : "l"(p));
    return a;
}

// Scratch (device globals)
__device__ float  g_cvox[NCLUST * VOXN];             // 32 MB
__device__ float  g_c1c[NCLUST * 4096 * 16];         // 67 MB, layout [c][sp][ic]
__device__ float  g_c2[NEDGE * 512 * 32];            // 67 MB, layout [e][sp][oc]
__device__ __align__(16) __half g_w2h[32 * 448];     // W2 fp16 [oc][tap*16+ic]
__device__ __align__(16) __half g_w3h[64 * 864];     // W3 fp16 [oc][tap*32+ic]
__device__ int    g_eidx_is_i64;
__device__ int    g_mask_is_u8;

// ---------------------------------------------------------------------------
// Kernel D: dtype layout detection
// ---------------------------------------------------------------------------
__global__ void detect_kernel(const int* __restrict__ eidx_w,
                              const unsigned int* __restrict__ mask_w,
                              int E, int maskWords)
{
    __shared__ int oddNZ, bigW;
    if (threadIdx.x == 0) { oddNZ = 0; bigW = 0; }
    __syncthreads();
    for (int i = threadIdx.x; i < E; i += blockDim.x)
        if (eidx_w[2 * i + 1] != 0) atomicOr(&oddNZ, 1);
    for (int i = threadIdx.x; i < maskWords; i += blockDim.x)
        if (mask_w[i] > 1u) atomicOr(&bigW, 1);
    __syncthreads();
    if (threadIdx.x == 0) {
        g_eidx_is_i64 = (oddNZ == 0) ? 1 : 0;
        g_mask_is_u8  = bigW;
    }
}

// ---------------------------------------------------------------------------
// Kernel W: W2 -> fp16 [oc][448]; W3 -> fp16 [oc][tap*32+ic]
// ---------------------------------------------------------------------------
__global__ void wtrans_kernel(const float* __restrict__ W2,
                              const float* __restrict__ W3)
{
    int i = blockIdx.x * blockDim.x + threadIdx.x;
    if (i < 64 * 32 * 27) {
        int oc = i / (32 * 27), r = i % (32 * 27), ic = r / 27, tap = r % 27;
        g_w3h[oc * 864 + tap * 32 + ic] = __float2half(W3[i]);
    }
    if (i < 32 * 448) {
        int oc = i / 448, k = i % 448;
        float v = 0.0f;
        if (k < 432) {
            int tap = k >> 4, ic = k & 15;
            v = W2[(oc * 16 + ic) * 27 + tap];
        }
        g_w2h[i] = __float2half(v);
    }
}

// ---------------------------------------------------------------------------
// Kernel 0: per-cluster voxelization (ovx/ovy/ovz tables, dynamic smem)
// ---------------------------------------------------------------------------
#define VOX_SMEM ((3 * NPT * VS + 4 * NPT + 6 * NPT) * 4)   // 54272 B

__global__ __launch_bounds__(256) void vox_kernel(
    const float* __restrict__ data,
    const int* __restrict__ clusts,
    const void* __restrict__ cmask)
{
    extern __shared__ __align__(16) float dsmv[];
    float* ovy = dsmv;
    float* ovz = dsmv + NPT * VS;
    float* ovx = dsmv + 2 * NPT * VS;
    float* sw  = dsmv + 3 * NPT * VS;
    float* spx = sw  + NPT;
    float* spy = spx + NPT;
    float* spz = spy + NPT;
    float* red = spz + NPT;

    const int c = blockIdx.x;
    const int t = threadIdx.x;
    const int mask_u8 = g_mask_is_u8;

    if (t < NPT) {
        int idx = clusts[c * NPT + t];
        int m;
        if (mask_u8) m = ((const unsigned char*)cmask)[c * NPT + t];
        else         m = ((const int*)cmask)[c * NPT + t];
        float x = data[idx * 5 + 0];
        float y = data[idx * 5 + 1];
        float z = data[idx * 5 + 2];
        float v = data[idx * 5 + 4];
        spx[t] = x; spy[t] = y; spz[t] = z;
        sw[t]  = m ? v : 0.0f;
        red[0*NPT + t] = m ? x :  1e9f;
        red[1*NPT + t] = m ? y :  1e9f;
        red[2*NPT + t] = m ? z :  1e9f;
        red[3*NPT + t] = m ? x : -1e9f;
        red[4*NPT + t] = m ? y : -1e9f;
        red[5*NPT + t] = m ? z : -1e9f;
    }
    __syncthreads();
    for (int s = 64; s > 0; s >>= 1) {
        if (t < s) {
            red[0*NPT + t] = fminf(red[0*NPT + t], red[0*NPT + t + s]);
            red[1*NPT + t] = fminf(red[1*NPT + t], red[1*NPT + t + s]);
            red[2*NPT + t] = fminf(red[2*NPT + t], red[2*NPT + t + s]);
            red[3*NPT + t] = fmaxf(red[3*NPT + t], red[3*NPT + t + s]);
            red[4*NPT + t] = fmaxf(red[4*NPT + t], red[4*NPT + t + s]);
            red[5*NPT + t] = fmaxf(red[5*NPT + t], red[5*NPT + t + s]);
        }
        __syncthreads();
    }
    const float minx = red[0], miny = red[NPT], minz = red[2*NPT];
    const float rx = red[3*NPT] - minx;
    const float ry = red[4*NPT] - miny;
    const float rz = red[5*NPT] - minz;
    const float mr = fmaxf(rx, fmaxf(ry, rz)) + 1.0f;
    const float gs  = 1.0f / mr;
    const float rgs = mr;
    const float ns  = 1.0f / (float)VS;

    {
        int p    = t & (NPT - 1);
        int half = t >> 7;
        float vx = (spx[p] - minx - rx * 0.5f - 0.5f) * gs + 0.5f;
        float vy = (spy[p] - miny - ry * 0.5f - 0.5f) * gs + 0.5f;
        float vz = (spz[p] - minz - rz * 0.5f - 0.5f) * gs + 0.5f;
        for (int b = half * 16; b < half * 16 + 16; ++b) {
            float lo = (float)b * ns;
            float ox = fminf(vx + gs, lo + ns) - fmaxf(vx, lo);
            float oy = fminf(vy + gs, lo + ns) - fmaxf(vy, lo);
            float oz = fminf(vz + gs, lo + ns) - fmaxf(vz, lo);
            ovx[p * VS + b] = fmaxf(ox, 0.0f) * rgs;
            ovy[p * VS + b] = fmaxf(oy, 0.0f) * rgs;
            ovz[p * VS + b] = fmaxf(oz, 0.0f) * rgs;
        }
    }
    __syncthreads();

    float* outp = g_cvox + (size_t)c * VOXN;
    for (int pass = 0; pass < 4; ++pass) {
        int jk = t + pass * 256;
        int j = jk >> 5, k = jk & 31;
        float acc[VS];
#pragma unroll
        for (int i = 0; i < VS; ++i) acc[i] = 0.0f;
        for (int p = 0; p < NPT; ++p) {
            float ty = sw[p] * ovy[p * VS + j];
            if (ty != 0.0f) {
                float tz = ty * ovz[p * VS + k];
                const float4* ox4 = (const float4*)&ovx[p * VS];
#pragma unroll
                for (int i4 = 0; i4 < 8; ++i4) {
                    float4 o = ox4[i4];
                    acc[i4 * 4 + 0] += o.x * tz;
                    acc[i4 * 4 + 1] += o.y * tz;
                    acc[i4 * 4 + 2] += o.z * tz;
                    acc[i4 * 4 + 3] += o.w * tz;
                }
            }
        }
#pragma unroll
        for (int i = 0; i < VS; ++i)
            outp[i * (VS * VS) + jk] = acc[i];
    }
}

// ---------------------------------------------------------------------------
// Kernel 1: per-CLUSTER linear conv1, z-slab tiling. Output [sp][ic].
// ---------------------------------------------------------------------------
#define C1SD 36
#define C1PL (33 * C1SD)     // 1188
#define C1SZ (9 * C1PL)      // 10692 floats

__global__ __launch_bounds__(256, 2) void conv1c_kernel(
    const float* __restrict__ W1)
{
    __shared__ __align__(16) float s_in[C1SZ];
    __shared__ __align__(16) float s_w[27 * 16];

    const int c    = blockIdx.x >> 2;
    const int slab = blockIdx.x & 3;
    const int t = threadIdx.x;
    const float* __restrict__ A = g_cvox + (size_t)c * VOXN;

    for (int i = t; i < C1SZ; i += 256) s_in[i] = 0.0f;
    for (int i = t; i < 432; i += 256) {
        int oc = i / 27, tap = i % 27;
        s_w[tap * 16 + oc] = W1[i];
    }
    __syncthreads();

    const int z0 = slab * 8;
#pragma unroll
    for (int r = 0; r < 9; ++r) {
        int i4 = t + r * 256;
        int zz = i4 >> 8, j = i4 & 255;
        int gz = z0 + zz;
        if (gz < 32) {
            float4 v = *(const float4*)&A[gz * 1024 + j * 4];
            *(float4*)&s_in[zz * C1PL + (j >> 3) * C1SD + (j & 7) * 4] = v;
        }
    }
    __syncthreads();

    const int x = t & 15, y = t >> 4;

    ull acc[4][8];
#pragma unroll
    for (int q = 0; q < 4; ++q)
#pragma unroll
        for (int m = 0; m < 8; ++m) acc[q][m] = 0ULL;

#pragma unroll
    for (int dz = 0; dz < 3; ++dz)
#pragma unroll
        for (int dy = 0; dy < 3; ++dy) {
            float2 v01[4];
            float  v2s[4];
#pragma unroll
            for (int q = 0; q < 4; ++q) {
                const int o = (2 * q + dz) * C1PL + (2 * y + dy) * C1SD + 2 * x;
                v01[q] = *(const float2*)&s_in[o];
                v2s[q] = s_in[o + 2];
            }
#pragma unroll
            for (int dx = 0; dx < 3; ++dx) {
                const int tap = (dz * 3 + dy) * 3 + dx;
                const ulonglong2 w01 = *(const ulonglong2*)&s_w[tap * 16];
                const ulonglong2 w23 = *(const ulonglong2*)&s_w[tap * 16 + 4];
                const ulonglong2 w45 = *(const ulonglong2*)&s_w[tap * 16 + 8];
                const ulonglong2 w67 = *(const ulonglong2*)&s_w[tap * 16 + 12];
#pragma unroll
                for (int q = 0; q < 4; ++q) {
                    float v = (dx == 0) ? v01[q].x : (dx == 1) ? v01[q].y : v2s[q];
                    ull vv = pk2(v, v);
                    fma2(acc[q][0], vv, w01.x);
                    fma2(acc[q][1], vv, w01.y);
                    fma2(acc[q][2], vv, w23.x);
                    fma2(acc[q][3], vv, w23.y);
                    fma2(acc[q][4], vv, w45.x);
                    fma2(acc[q][5], vv, w45.y);
                    fma2(acc[q][6], vv, w67.x);
                    fma2(acc[q][7], vv, w67.y);
                }
            }
        }

    float* outp = g_c1c + (size_t)c * 4096 * 16;
#pragma unroll
    for (int q = 0; q < 4; ++q) {
        const int oz = slab * 4 + q;
        const int sp = oz * 256 + y * 16 + x;
        float vals[16];
#pragma unroll
        for (int m = 0; m < 8; ++m) {
            float2 p = upk2(acc[q][m]);
            vals[2 * m] = p.x; vals[2 * m + 1] = p.y;
        }
        float4* o4 = (float4*)(outp + sp * 16);
#pragma unroll
        for (int w = 0; w < 4; ++w) o4[w] = ((float4*)vals)[w];
    }
}

// ---------------------------------------------------------------------------
// Kernel 2: conv2 via mma.sync m16n8k16. 256 thr / 8 warps, 2 CTAs/SM.
// Output layout: g_c2 [e][sp][oc] (coalesced for conv3 fill).
// ---------------------------------------------------------------------------
#define C2_B_ROWB   912
#define C2_B_BYTES  (32 * C2_B_ROWB)           // 29184
#define C2_ACT_BYTES (5 * 17 * 18 * 48)        // 73440
#define C2MM_SMEM   (C2_B_BYTES + C2_ACT_BYTES + 256)

__global__ __launch_bounds__(256) void conv2_mma_kernel(
    const int* __restrict__ eidx,
    const float* __restrict__ b2,
    const float* __restrict__ b1,
    int E, int C)
{
    extern __shared__ __align__(16) char sm2[];
    char*  sB     = sm2;
    char*  sAct   = sm2 + C2_B_BYTES;
    float* sStage = (float*)sAct;               // ALIAS: act dead when staging
    float* sB1    = (float*)(sm2 + C2_B_BYTES + C2_ACT_BYTES);
    float* sB2    = sB1 + 16;

    const int e = blockIdx.x;
    const int t = threadIdx.x;
    const int w = t >> 5, lane = t & 31;

    int ca, cb;
    if (g_eidx_is_i64) { ca = eidx[2 * e]; cb = eidx[2 * (E + e)]; }
    else               { ca = eidx[e];     cb = eidx[E + e];       }
    ca = min(max(ca, 0), C - 1);
    cb = min(max(cb, 0), C - 1);

    if (t < 16) sB1[t] = b1[t];
    if (t >= 32 && t < 64) sB2[t - 32] = b2[t - 32];

    {
        const unsigned* w2u = (const unsigned*)g_w2h;
        for (int j = t; j < 32 * 224; j += 256) {
            int row = j / 224, ku = j % 224;
            *(unsigned*)(sB + row * C2_B_ROWB + ku * 4) = w2u[j];
        }
    }
    __syncthreads();

    const float4* __restrict__ A4 = (const float4*)(g_c1c + (size_t)ca * 65536);
    const float4* __restrict__ B4 = (const float4*)(g_c1c + (size_t)cb * 65536);
    const float4* b1q = (const float4*)sB1;

    const int xr   = lane & 7;
    const int ysel = (lane >> 3) & 1;
    const int hh   = (lane >> 4) & 1;
    const int zloc = w & 1, ypair = w >> 1;
    const unsigned actB = smem_u32(sAct);
    const unsigned bBs  = smem_u32(sB);
    const int bgrp = lane >> 3, brow = lane & 7;
    const unsigned bAddr0 = bBs + (unsigned)(((bgrp >> 1) * 8 + brow) * C2_B_ROWB
                                             + (bgrp & 1) * 16);
    float* stage = sStage + w * (16 * 34);
    float* outp = g_c2 + (size_t)e * 16384;

    for (int t2 = 0; t2 < 4; ++t2) {
        for (int r = 0; r < 23; ++r) {
            int i = t + r * 256;
            if (i < 5780) {
                int icq = i & 3, v = i >> 2;
                int p = v / 289, rem = v % 289, yy = rem / 17, xx = rem % 17;
                int zz = t2 * 4 + p;
                uint2 st = make_uint2(0u, 0u);
                if (zz < 16 && yy < 16 && xx < 16) {
                    int gi = ((zz * 16 + yy) * 16 + xx) * 4 + icq;
                    float4 a = A4[gi], b = B4[gi], bb = b1q[icq];
                    __half2 h0 = __floats2half2_rn(fmaxf(a.x + b.x + bb.x, 0.0f),
                                                   fmaxf(a.y + b.y + bb.y, 0.0f));
                    __half2 h1 = __floats2half2_rn(fmaxf(a.z + b.z + bb.z, 0.0f),
                                                   fmaxf(a.w + b.w + bb.w, 0.0f));
                    st.x = *(unsigned*)&h0;
                    st.y = *(unsigned*)&h1;
                }
                int voff = ((p * 17 + yy) * 18 + (xx & 1) * 9 + (xx >> 1)) * 48 + icq * 8;
                *(uint2*)(sAct + voff) = st;
            }
        }
        __syncthreads();

        float acc[16];
#pragma unroll
        for (int q = 0; q < 16; ++q) acc[q] = 0.0f;

#pragma unroll
        for (int dz = 0; dz < 3; ++dz)
#pragma unroll
            for (int dy = 0; dy < 3; ++dy)
#pragma unroll
                for (int dx = 0; dx < 3; ++dx) {
                    const int g = (dz * 3 + dy) * 3 + dx;
                    unsigned bf[8];
                    {
                        unsigned a0 = bAddr0 + (unsigned)(g * 32);
                        asm volatile(
                            "ldmatrix.sync.aligned.m8n8.x4.shared.b16 {%0,%1,%2,%3}, [%4];"
                            : "=r"(bf[0]), "=r"(bf[1]), "=r"(bf[2]), "=r"(bf[3])
                            : "r"(a0));
                        asm volatile(
                            "ldmatrix.sync.aligned.m8n8.x4.shared.b16 {%0,%1,%2,%3}, [%4];"
                            : "=r"(bf[4]), "=r"(bf[5]), "=r"(bf[6]), "=r"(bf[7])
                            : "r"(a0 + 16u * C2_B_ROWB));
                    }
                    const int p = 2 * zloc + dz;
                    const int parity = dx & 1;
                    const int xh = xr + (dx >> 1);
                    const int yv = 4 * ypair + 2 * ysel + dy;
                    unsigned aAddr = actB
                        + (unsigned)(((p * 17 + yv) * 18 + parity * 9 + xh) * 48
                                     + hh * 16);
                    unsigned af[4];
                    asm volatile(
                        "ldmatrix.sync.aligned.m8n8.x4.shared.b16 {%0,%1,%2,%3}, [%4];"
                        : "=r"(af[0]), "=r"(af[1]), "=r"(af[2]), "=r"(af[3])
                        : "r"(aAddr));
#pragma unroll
                    for (int nt = 0; nt < 4; ++nt) {
                        float* c = &acc[nt * 4];
                        asm volatile(
                            "mma.sync.aligned.m16n8k16.row.col.f32.f16.f16.f32 "
                            "{%0,%1,%2,%3}, {%4,%5,%6,%7}, {%8,%9}, {%0,%1,%2,%3};"
                            : "+f"(c[0]), "+f"(c[1]), "+f"(c[2]), "+f"(c[3])
                            : "r"(af[0]), "r"(af[1]), "r"(af[2]), "r"(af[3]),
                              "r"(bf[nt * 2]), "r"(bf[nt * 2 + 1]));
                    }
                }

        __syncthreads();   // act dead -> stage may overwrite

        {
            const int row = lane >> 2, col2 = (lane & 3) * 2;
#pragma unroll
            for (int nt = 0; nt < 4; ++nt) {
                const int cb0 = nt * 8 + col2;
                *(float2*)&stage[row * 34 + cb0]       =
                    make_float2(acc[nt * 4 + 0], acc[nt * 4 + 1]);
                *(float2*)&stage[(row + 8) * 34 + cb0] =
                    make_float2(acc[nt * 4 + 2], acc[nt * 4 + 3]);
            }
            __syncwarp();
            {
                const int spq = lane & 15, half = lane >> 4;
                const int z = t2 * 2 + zloc;
                const int spg = z * 64 + ypair * 16 + spq;
                float o[16];
#pragma unroll
                for (int j = 0; j < 16; ++j)
                    o[j] = fmaxf(stage[spq * 34 + half * 16 + j] + sB2[half * 16 + j],
                                 0.0f);
                float4* dst = (float4*)&outp[spg * 32 + half * 16];
#pragma unroll
                for (int q = 0; q < 4; ++q) dst[q] = ((float4*)o)[q];
            }
        }
        __syncthreads();
    }
}

// ---------------------------------------------------------------------------
// Kernel 3: conv3 via mma.sync m16n8k16 + relu + mean-pool + FC.
// Per edge: D[64 sp, 64 oc] = im2col[64, 864] x W3^T.
// 8 warps = (m-tile 0..3, oc-half 0..1). Weights streamed in 3 k-chunks.
// ---------------------------------------------------------------------------
#define C3_ACT_B   64800        // 9 planes x 9 y x 10 x-slots x 80B... (9*9*800)
#define C3_W_ROWB  592
#define C3_W_B     (64 * C3_W_ROWB)     // 37888
#define C3MM_SMEM  (C3_ACT_B + C3_W_B + 512)

__global__ __launch_bounds__(256) void conv3_mma_kernel(
    const float* __restrict__ b3,
    const float* __restrict__ Wfc,
    const float* __restrict__ bfc,
    float* __restrict__ out)
{
    extern __shared__ __align__(16) char sm3[];
    char*  sAct   = sm3;
    char*  sW     = sm3 + C3_ACT_B;
    float* sStage = (float*)sW;                    // alias after mma done
    float* sB3    = (float*)(sm3 + C3_ACT_B + C3_W_B);
    float* sPooled = sB3 + 64;

    const int e = blockIdx.x;
    const int t = threadIdx.x;
    const int w = t >> 5, lane = t & 31;

    if (t < 64) sB3[t] = b3[t];

    // zero act (pads), then fill data voxels
    for (int i = t; i < C3_ACT_B / 4; i += 256) ((unsigned*)sAct)[i] = 0u;
    __syncthreads();
    {
        const float4* src = (const float4*)(g_c2 + (size_t)e * 16384);
        for (int i = t; i < 4096; i += 256) {
            int sp = i >> 3, part = i & 7;
            float4 v = src[sp * 8 + part];
            __half2 h0 = __floats2half2_rn(v.x, v.y);
            __half2 h1 = __floats2half2_rn(v.z, v.w);
            int x = sp & 7, y = (sp >> 3) & 7, z = sp >> 6;
            int va = z * 7200 + y * 800 + ((x & 1) * 5 + (x >> 1)) * 80 + part * 8;
            uint2 st;
            st.x = *(unsigned*)&h0;
            st.y = *(unsigned*)&h1;
            *(uint2*)(sAct + va) = st;
        }
    }

    const int mt = w & 3, nh = w >> 2;
    const int lx = lane & 3, ysub = (lane >> 2) & 1;
    const int ysel = (lane >> 3) & 1, hh = lane >> 4;
    const int ly = ysel * 2 + ysub;
    const unsigned actB = smem_u32(sAct);
    const unsigned wBs  = smem_u32(sW);
    const int bgrp = lane >> 3, brow = lane & 7;
    const unsigned bAddr0 = wBs + (unsigned)((nh * 32 + (bgrp >> 1) * 8 + brow) * C3_W_ROWB
                                             + (bgrp & 1) * 16);

    float acc[16];
#pragma unroll
    for (int q = 0; q < 16; ++q) acc[q] = 0.0f;

    const unsigned* w3u = (const unsigned*)g_w3h;   // [64][432] u32

    for (int c = 0; c < 3; ++c) {
        __syncthreads();
        for (int j = t; j < 64 * 144; j += 256) {
            int oc = j / 144, jj = j % 144;
            *(unsigned*)(sW + oc * C3_W_ROWB + jj * 4) = w3u[oc * 432 + c * 144 + jj];
        }
        __syncthreads();
#pragma unroll
        for (int gl = 0; gl < 18; ++gl) {
            const int g = c * 18 + gl;
            const int tap = g >> 1, ih = g & 1;
            const int dz = tap / 9, dyr = (tap % 9) / 3, dx = tap % 3;
            const int xp = 2 * lx + dx;
            unsigned aAddr = actB
                + (unsigned)((2 * mt + dz) * 7200 + (2 * ly + dyr) * 800
                             + ((xp & 1) * 5 + (xp >> 1)) * 80 + ih * 32 + hh * 16);
            unsigned af[4];
            asm volatile(
                "ldmatrix.sync.aligned.m8n8.x4.shared.b16 {%0,%1,%2,%3}, [%4];"
                : "=r"(af[0]), "=r"(af[1]), "=r"(af[2]), "=r"(af[3])
                : "r"(aAddr));
            unsigned bf[8];
            {
                unsigned a0 = bAddr0 + (unsigned)(gl * 32);
                asm volatile(
                    "ldmatrix.sync.aligned.m8n8.x4.shared.b16 {%0,%1,%2,%3}, [%4];"
                    : "=r"(bf[0]), "=r"(bf[1]), "=r"(bf[2]), "=r"(bf[3])
                    : "r"(a0));
                asm volatile(
                    "ldmatrix.sync.aligned.m8n8.x4.shared.b16 {%0,%1,%2,%3}, [%4];"
                    : "=r"(bf[4]), "=r"(bf[5]), "=r"(bf[6]), "=r"(bf[7])
                    : "r"(a0 + 16u * C3_W_ROWB));
            }
#pragma unroll
            for (int nt = 0; nt < 4; ++nt) {
                float* cc = &acc[nt * 4];
                asm volatile(
                    "mma.sync.aligned.m16n8k16.row.col.f32.f16.f16.f32 "
                    "{%0,%1,%2,%3}, {%4,%5,%6,%7}, {%8,%9}, {%0,%1,%2,%3};"
                    : "+f"(cc[0]), "+f"(cc[1]), "+f"(cc[2]), "+f"(cc[3])
                    : "r"(af[0]), "r"(af[1]), "r"(af[2]), "r"(af[3]),
                      "r"(bf[nt * 2]), "r"(bf[nt * 2 + 1]));
            }
        }
    }
    __syncthreads();   // weights dead -> stage may overwrite

    {
        const int row = lane >> 2, col2 = (lane & 3) * 2;
#pragma unroll
        for (int nt = 0; nt < 4; ++nt) {
            const int oc0 = nh * 32 + nt * 8 + col2;
            const int sp0 = mt * 16 + row;
            sStage[sp0 * 66 + oc0]
                = fmaxf(acc[nt * 4 + 0] + sB3[oc0], 0.0f);
            sStage[sp0 * 66 + oc0 + 1]
                = fmaxf(acc[nt * 4 + 1] + sB3[oc0 + 1], 0.0f);
            sStage[(sp0 + 8) * 66 + oc0]
                = fmaxf(acc[nt * 4 + 2] + sB3[oc0], 0.0f);
            sStage[(sp0 + 8) * 66 + oc0 + 1]
                = fmaxf(acc[nt * 4 + 3] + sB3[oc0 + 1], 0.0f);
        }
    }
    __syncthreads();
    if (t < 64) {
        float s = 0.0f;
#pragma unroll 8
        for (int sp = 0; sp < 64; ++sp) s += sStage[sp * 66 + t];
        sPooled[t] = s * (1.0f / 64.0f);
    }
    __syncthreads();
    if (t < 64) {
        float r = bfc[t];
#pragma unroll 8
        for (int ic = 0; ic < 64; ++ic)
            r += sPooled[ic] * __ldg(&Wfc[ic * 64 + t]);
        out[e * 64 + t] = r;
    }
}

// ---------------------------------------------------------------------------
extern "C" void kernel_launch(void* const* d_in, const int* in_sizes, int n_in,
                              void* d_out, int out_size)
{
    const float* data   = (const float*)d_in[0];
    const int*   clusts = (const int*)d_in[1];
    const void*  cmask  = d_in[2];
    const int*   eidx   = (const int*)d_in[3];
    const float* W1     = (const float*)d_in[4];
    const float* b1     = (const float*)d_in[5];
    const float* W2     = (const float*)d_in[6];
    const float* b2     = (const float*)d_in[7];
    const float* W3     = (const float*)d_in[8];
    const float* b3     = (const float*)d_in[9];
    const float* Wfc    = (const float*)d_in[10];
    const float* bfc    = (const float*)d_in[11];
    float*       out    = (float*)d_out;

    const int C = in_sizes[1] / NPT;   // 256
    const int E = in_sizes[3] / 2;     // 1024
    const int maskWords = in_sizes[2] / 4;

    cudaFuncSetAttribute(vox_kernel,
        cudaFuncAttributeMaxDynamicSharedMemorySize, VOX_SMEM);
    cudaFuncSetAttribute(conv2_mma_kernel,
        cudaFuncAttributeMaxDynamicSharedMemorySize, C2MM_SMEM);
    cudaFuncSetAttribute(conv3_mma_kernel,
        cudaFuncAttributeMaxDynamicSharedMemorySize, C3MM_SMEM);

    detect_kernel<<<1, 256>>>(eidx, (const unsigned int*)cmask, E, maskWords);
    wtrans_kernel<<<216, 256>>>(W2, W3);
    vox_kernel<<<C, 256, VOX_SMEM>>>(data, clusts, cmask);
    conv1c_kernel<<<C * 4, 256>>>(W1);
    conv2_mma_kernel<<<E, 256, C2MM_SMEM>>>(eidx, b2, b1, E, C);
    conv3_mma_kernel<<<E, 256, C3MM_SMEM>>>(b3, Wfc, bfc, out);
}

// round 14
// speedup vs baseline: 1.9560x; 1.2000x over previous
#include <cuda_runtime.h>
#include <cuda_bf16.h>
#include <cuda_fp16.h>

#define NCLUST 256
#define NPT    128
#define NEDGE  1024
#define VS     32
#define VOXN   (VS*VS*VS)   // 32768

typedef unsigned long long ull;

__device__ __forceinline__ ull pk2(float lo, float hi) {
    ull r; asm("mov.b64 %0, {%1,%2};" : "=l"(r) : "f"(lo), "f"(hi)); return r;
}
__device__ __forceinline__ void fma2(ull& d, ull a, ull b) {
    asm("fma.rn.f32x2 %0, %1, %2, %0;" : "+l"(d) : "l"(a), "l"(b));
}
__device__ __forceinline__ float2 upk2(ull v) {
    float2 r; asm("mov.b64 {%0,%1}, %2;" : "=f"(r.x), "=f"(r.y) : "l"(v)); return r;
}
__device__ __forceinline__ unsigned smem_u32(const void* p) {
    unsigned a;
    asm("{ .reg .u64 t; cvta.to.shared.u64 t, %1; cvt.u32.u64 %0, t; }" : "=r"(a) : "l"(p));
    return a;
}

// Scratch (device globals)
__device__ float  g_cvox[NCLUST * VOXN];             // 32 MB
__device__ float  g_c1c[NCLUST * 4096 * 16];         // 67 MB, [c][sp][ic]
__device__ float  g_c2[NEDGE * 512 * 32];            // 67 MB, [e][sp][oc]
__device__ __align__(16) __half g_acth[NEDGE * 4096 * 16];  // 134 MB, [e][sp][ic] fp16
__device__ __align__(16) float g_ovx[NCLUST * NPT * VS];    // 4 MB
__device__ __align__(16) float g_ovy[NCLUST * NPT * VS];
__device__ __align__(16) float g_ovz[NCLUST * NPT * VS];
__device__ __align__(16) float g_swt[NCLUST * NPT];
__device__ __align__(16) __half g_w2h[32 * 448];     // W2 fp16 [oc][tap*16+ic]
__device__ __align__(16) __half g_w3h[64 * 864];     // W3 fp16 [oc][tap*32+ic]
__device__ int    g_eidx_is_i64;
__device__ int    g_mask_is_u8;

// ---------------------------------------------------------------------------
// Kernel D: dtype layout detection
// ---------------------------------------------------------------------------
__global__ void detect_kernel(const int* __restrict__ eidx_w,
                              const unsigned int* __restrict__ mask_w,
                              int E, int maskWords)
{
    __shared__ int oddNZ, bigW;
    if (threadIdx.x == 0) { oddNZ = 0; bigW = 0; }
    __syncthreads();
    for (int i = threadIdx.x; i < E; i += blockDim.x)
        if (eidx_w[2 * i + 1] != 0) atomicOr(&oddNZ, 1);
    for (int i = threadIdx.x; i < maskWords; i += blockDim.x)
        if (mask_w[i] > 1u) atomicOr(&bigW, 1);
    __syncthreads();
    if (threadIdx.x == 0) {
        g_eidx_is_i64 = (oddNZ == 0) ? 1 : 0;
        g_mask_is_u8  = bigW;
    }
}

// ---------------------------------------------------------------------------
// Kernel W: W2 -> fp16 [oc][448]; W3 -> fp16 [oc][tap*32+ic]
// ---------------------------------------------------------------------------
__global__ void wtrans_kernel(const float* __restrict__ W2,
                              const float* __restrict__ W3)
{
    int i = blockIdx.x * blockDim.x + threadIdx.x;
    if (i < 64 * 32 * 27) {
        int oc = i / (32 * 27), r = i % (32 * 27), ic = r / 27, tap = r % 27;
        g_w3h[oc * 864 + tap * 32 + ic] = __float2half(W3[i]);
    }
    if (i < 32 * 448) {
        int oc = i / 448, k = i % 448;
        float v = 0.0f;
        if (k < 432) {
            int tap = k >> 4, ic = k & 15;
            v = W2[(oc * 16 + ic) * 27 + tap];
        }
        g_w2h[i] = __float2half(v);
    }
}

// ---------------------------------------------------------------------------
// Kernel 0a: per-cluster reduction + overlap tables -> gmem (once per cluster)
// ---------------------------------------------------------------------------
__global__ __launch_bounds__(256) void vox_tab_kernel(
    const float* __restrict__ data,
    const int* __restrict__ clusts,
    const void* __restrict__ cmask)
{
    __shared__ __align__(16) float spx[NPT], spy[NPT], spz[NPT];
    __shared__ __align__(16) float red[6 * NPT];

    const int c = blockIdx.x;
    const int t = threadIdx.x;
    const int mask_u8 = g_mask_is_u8;

    if (t < NPT) {
        int idx = clusts[c * NPT + t];
        int m;
        if (mask_u8) m = ((const unsigned char*)cmask)[c * NPT + t];
        else         m = ((const int*)cmask)[c * NPT + t];
        float x = data[idx * 5 + 0];
        float y = data[idx * 5 + 1];
        float z = data[idx * 5 + 2];
        float v = data[idx * 5 + 4];
        spx[t] = x; spy[t] = y; spz[t] = z;
        g_swt[c * NPT + t] = m ? v : 0.0f;
        red[0*NPT + t] = m ? x :  1e9f;
        red[1*NPT + t] = m ? y :  1e9f;
        red[2*NPT + t] = m ? z :  1e9f;
        red[3*NPT + t] = m ? x : -1e9f;
        red[4*NPT + t] = m ? y : -1e9f;
        red[5*NPT + t] = m ? z : -1e9f;
    }
    __syncthreads();
    for (int s = 64; s > 0; s >>= 1) {
        if (t < s) {
            red[0*NPT + t] = fminf(red[0*NPT + t], red[0*NPT + t + s]);
            red[1*NPT + t] = fminf(red[1*NPT + t], red[1*NPT + t + s]);
            red[2*NPT + t] = fminf(red[2*NPT + t], red[2*NPT + t + s]);
            red[3*NPT + t] = fmaxf(red[3*NPT + t], red[3*NPT + t + s]);
            red[4*NPT + t] = fmaxf(red[4*NPT + t], red[4*NPT + t + s]);
            red[5*NPT + t] = fmaxf(red[5*NPT + t], red[5*NPT + t + s]);
        }
        __syncthreads();
    }
    const float minx = red[0], miny = red[NPT], minz = red[2*NPT];
    const float rx = red[3*NPT] - minx;
    const float ry = red[4*NPT] - miny;
    const float rz = red[5*NPT] - minz;
    const float mr = fmaxf(rx, fmaxf(ry, rz)) + 1.0f;
    const float gs  = 1.0f / mr;
    const float rgs = mr;
    const float ns  = 1.0f / (float)VS;

    {
        int p    = t & (NPT - 1);
        int half = t >> 7;
        float vx = (spx[p] - minx - rx * 0.5f - 0.5f) * gs + 0.5f;
        float vy = (spy[p] - miny - ry * 0.5f - 0.5f) * gs + 0.5f;
        float vz = (spz[p] - minz - rz * 0.5f - 0.5f) * gs + 0.5f;
        for (int b = half * 16; b < half * 16 + 16; ++b) {
            float lo = (float)b * ns;
            float ox = fminf(vx + gs, lo + ns) - fmaxf(vx, lo);
            float oy = fminf(vy + gs, lo + ns) - fmaxf(vy, lo);
            float oz = fminf(vz + gs, lo + ns) - fmaxf(vz, lo);
            g_ovx[c * NPT * VS + p * VS + b] = fmaxf(ox, 0.0f) * rgs;
            g_ovy[c * NPT * VS + p * VS + b] = fmaxf(oy, 0.0f) * rgs;
            g_ovz[c * NPT * VS + p * VS + b] = fmaxf(oz, 0.0f) * rgs;
        }
    }
}

// ---------------------------------------------------------------------------
// Kernel 0b: accumulate. grid (C, 4), tables smem-cached from gmem.
// ---------------------------------------------------------------------------
#define VOXA_SMEM ((3 * NPT * VS + NPT) * 4)   // 49664 B

__global__ __launch_bounds__(256) void vox_acc_kernel()
{
    extern __shared__ __align__(16) float dsmv[];
    float* ovy = dsmv;
    float* ovz = dsmv + NPT * VS;
    float* ovx = dsmv + 2 * NPT * VS;
    float* sw  = dsmv + 3 * NPT * VS;

    const int c = blockIdx.x;
    const int pass = blockIdx.y;
    const int t = threadIdx.x;

    {
        const float4* sy = (const float4*)(g_ovy + c * NPT * VS);
        const float4* sz = (const float4*)(g_ovz + c * NPT * VS);
        const float4* sx = (const float4*)(g_ovx + c * NPT * VS);
#pragma unroll
        for (int r = 0; r < 4; ++r) {
            int i = t + r * 256;
            ((float4*)ovy)[i] = sy[i];
            ((float4*)ovz)[i] = sz[i];
            ((float4*)ovx)[i] = sx[i];
        }
        if (t < NPT) sw[t] = g_swt[c * NPT + t];
    }
    __syncthreads();

    float* outp = g_cvox + (size_t)c * VOXN;
    {
        int jk = t + pass * 256;
        int j = jk >> 5, k = jk & 31;
        float acc[VS];
#pragma unroll
        for (int i = 0; i < VS; ++i) acc[i] = 0.0f;
        for (int p = 0; p < NPT; ++p) {
            float ty = sw[p] * ovy[p * VS + j];
            if (ty != 0.0f) {
                float tz = ty * ovz[p * VS + k];
                const float4* ox4 = (const float4*)&ovx[p * VS];
#pragma unroll
                for (int i4 = 0; i4 < 8; ++i4) {
                    float4 o = ox4[i4];
                    acc[i4 * 4 + 0] += o.x * tz;
                    acc[i4 * 4 + 1] += o.y * tz;
                    acc[i4 * 4 + 2] += o.z * tz;
                    acc[i4 * 4 + 3] += o.w * tz;
                }
            }
        }
#pragma unroll
        for (int i = 0; i < VS; ++i)
            outp[i * (VS * VS) + jk] = acc[i];
    }
}

// ---------------------------------------------------------------------------
// Kernel 1: per-CLUSTER linear conv1, z-slab tiling. Output [sp][ic].
// ---------------------------------------------------------------------------
#define C1SD 36
#define C1PL (33 * C1SD)     // 1188
#define C1SZ (9 * C1PL)      // 10692 floats

__global__ __launch_bounds__(256, 2) void conv1c_kernel(
    const float* __restrict__ W1)
{
    __shared__ __align__(16) float s_in[C1SZ];
    __shared__ __align__(16) float s_w[27 * 16];

    const int c    = blockIdx.x >> 2;
    const int slab = blockIdx.x & 3;
    const int t = threadIdx.x;
    const float* __restrict__ A = g_cvox + (size_t)c * VOXN;

    for (int i = t; i < C1SZ; i += 256) s_in[i] = 0.0f;
    for (int i = t; i < 432; i += 256) {
        int oc = i / 27, tap = i % 27;
        s_w[tap * 16 + oc] = W1[i];
    }
    __syncthreads();

    const int z0 = slab * 8;
#pragma unroll
    for (int r = 0; r < 9; ++r) {
        int i4 = t + r * 256;
        int zz = i4 >> 8, j = i4 & 255;
        int gz = z0 + zz;
        if (gz < 32) {
            float4 v = *(const float4*)&A[gz * 1024 + j * 4];
            *(float4*)&s_in[zz * C1PL + (j >> 3) * C1SD + (j & 7) * 4] = v;
        }
    }
    __syncthreads();

    const int x = t & 15, y = t >> 4;

    ull acc[4][8];
#pragma unroll
    for (int q = 0; q < 4; ++q)
#pragma unroll
        for (int m = 0; m < 8; ++m) acc[q][m] = 0ULL;

#pragma unroll
    for (int dz = 0; dz < 3; ++dz)
#pragma unroll
        for (int dy = 0; dy < 3; ++dy) {
            float2 v01[4];
            float  v2s[4];
#pragma unroll
            for (int q = 0; q < 4; ++q) {
                const int o = (2 * q + dz) * C1PL + (2 * y + dy) * C1SD + 2 * x;
                v01[q] = *(const float2*)&s_in[o];
                v2s[q] = s_in[o + 2];
            }
#pragma unroll
            for (int dx = 0; dx < 3; ++dx) {
                const int tap = (dz * 3 + dy) * 3 + dx;
                const ulonglong2 w01 = *(const ulonglong2*)&s_w[tap * 16];
                const ulonglong2 w23 = *(const ulonglong2*)&s_w[tap * 16 + 4];
                const ulonglong2 w45 = *(const ulonglong2*)&s_w[tap * 16 + 8];
                const ulonglong2 w67 = *(const ulonglong2*)&s_w[tap * 16 + 12];
#pragma unroll
                for (int q = 0; q < 4; ++q) {
                    float v = (dx == 0) ? v01[q].x : (dx == 1) ? v01[q].y : v2s[q];
                    ull vv = pk2(v, v);
                    fma2(acc[q][0], vv, w01.x);
                    fma2(acc[q][1], vv, w01.y);
                    fma2(acc[q][2], vv, w23.x);
                    fma2(acc[q][3], vv, w23.y);
                    fma2(acc[q][4], vv, w45.x);
                    fma2(acc[q][5], vv, w45.y);
                    fma2(acc[q][6], vv, w67.x);
                    fma2(acc[q][7], vv, w67.y);
                }
            }
        }

    float* outp = g_c1c + (size_t)c * 4096 * 16;
#pragma unroll
    for (int q = 0; q < 4; ++q) {
        const int oz = slab * 4 + q;
        const int sp = oz * 256 + y * 16 + x;
        float vals[16];
#pragma unroll
        for (int m = 0; m < 8; ++m) {
            float2 p = upk2(acc[q][m]);
            vals[2 * m] = p.x; vals[2 * m + 1] = p.y;
        }
        float4* o4 = (float4*)(outp + sp * 16);
#pragma unroll
        for (int w = 0; w < 4; ++w) o4[w] = ((float4*)vals)[w];
    }
}

// ---------------------------------------------------------------------------
// Kernel F: per-edge fused activation fp16: relu(linA+linB+b1) -> g_acth
// ---------------------------------------------------------------------------
__global__ __launch_bounds__(256) void fuseact_kernel(
    const int* __restrict__ eidx,
    const float* __restrict__ b1,
    int E, int C)
{
    const int e = blockIdx.x;
    const int t = threadIdx.x;

    int ca, cb;
    if (g_eidx_is_i64) { ca = eidx[2 * e]; cb = eidx[2 * (E + e)]; }
    else               { ca = eidx[e];     cb = eidx[E + e];       }
    ca = min(max(ca, 0), C - 1);
    cb = min(max(cb, 0), C - 1);

    const float4* __restrict__ A4 = (const float4*)(g_c1c + (size_t)ca * 65536);
    const float4* __restrict__ B4 = (const float4*)(g_c1c + (size_t)cb * 65536);
    uint2* __restrict__ dst = (uint2*)(g_acth + (size_t)e * 65536);

    float4 bb[4];
#pragma unroll
    for (int q = 0; q < 4; ++q) bb[q] = __ldg((const float4*)b1 + q);

#pragma unroll
    for (int r = 0; r < 64; ++r) {
        int i = t + r * 256;             // 0..16383, icq = i & 3
        float4 a = A4[i], b = B4[i];
        float4 bi = bb[i & 3];
        __half2 h0 = __floats2half2_rn(fmaxf(a.x + b.x + bi.x, 0.0f),
                                       fmaxf(a.y + b.y + bi.y, 0.0f));
        __half2 h1 = __floats2half2_rn(fmaxf(a.z + b.z + bi.z, 0.0f),
                                       fmaxf(a.w + b.w + bi.w, 0.0f));
        uint2 st;
        st.x = *(unsigned*)&h0;
        st.y = *(unsigned*)&h1;
        dst[i] = st;
    }
}

// ---------------------------------------------------------------------------
// Kernel 2: conv2 via mma.sync m16n8k16. Fill = fp16 copy from g_acth.
// ---------------------------------------------------------------------------
#define C2_B_ROWB   912
#define C2_B_BYTES  (32 * C2_B_ROWB)           // 29184
#define C2_ACT_BYTES (5 * 17 * 18 * 48)        // 73440
#define C2MM_SMEM   (C2_B_BYTES + C2_ACT_BYTES + 256)

__global__ __launch_bounds__(256) void conv2_mma_kernel(
    const float* __restrict__ b2)
{
    extern __shared__ __align__(16) char sm2[];
    char*  sB     = sm2;
    char*  sAct   = sm2 + C2_B_BYTES;
    float* sStage = (float*)sAct;               // ALIAS: act dead when staging
    float* sB2    = (float*)(sm2 + C2_B_BYTES + C2_ACT_BYTES);

    const int e = blockIdx.x;
    const int t = threadIdx.x;
    const int w = t >> 5, lane = t & 31;

    if (t < 32) sB2[t] = b2[t];

    {
        const unsigned* w2u = (const unsigned*)g_w2h;
        for (int j = t; j < 32 * 224; j += 256) {
            int row = j / 224, ku = j % 224;
            *(unsigned*)(sB + row * C2_B_ROWB + ku * 4) = w2u[j];
        }
    }
    __syncthreads();

    const uint4* __restrict__ actq = (const uint4*)(g_acth + (size_t)e * 65536);

    const int xr   = lane & 7;
    const int ysel = (lane >> 3) & 1;
    const int hh   = (lane >> 4) & 1;
    const int zloc = w & 1, ypair = w >> 1;
    const unsigned actB = smem_u32(sAct);
    const unsigned bBs  = smem_u32(sB);
    const int bgrp = lane >> 3, brow = lane & 7;
    const unsigned bAddr0 = bBs + (unsigned)(((bgrp >> 1) * 8 + brow) * C2_B_ROWB
                                             + (bgrp & 1) * 16);
    float* stage = sStage + w * (16 * 34);
    float* outp = g_c2 + (size_t)e * 16384;

    for (int t2 = 0; t2 < 4; ++t2) {
        // ---- fill: pure fp16 copy, 6 iters x (2 LDG.128 + 2 STS.128)
#pragma unroll
        for (int r = 0; r < 6; ++r) {
            int i = t + r * 256;
            if (i < 1445) {
                int p = i / 289, rem = i % 289, yy = rem / 17, xx = rem % 17;
                int zz = t2 * 4 + p;
                uint4 u0 = make_uint4(0u, 0u, 0u, 0u), u1 = u0;
                if (zz < 16 && yy < 16 && xx < 16) {
                    int sp = (zz * 16 + yy) * 16 + xx;
                    u0 = actq[sp * 2];
                    u1 = actq[sp * 2 + 1];
                }
                int voff = ((p * 17 + yy) * 18 + (xx & 1) * 9 + (xx >> 1)) * 48;
                *(uint4*)(sAct + voff)      = u0;
                *(uint4*)(sAct + voff + 16) = u1;
            }
        }
        __syncthreads();

        float acc[16];
#pragma unroll
        for (int q = 0; q < 16; ++q) acc[q] = 0.0f;

#pragma unroll
        for (int dz = 0; dz < 3; ++dz)
#pragma unroll
            for (int dy = 0; dy < 3; ++dy)
#pragma unroll
                for (int dx = 0; dx < 3; ++dx) {
                    const int g = (dz * 3 + dy) * 3 + dx;
                    unsigned bf[8];
                    {
                        unsigned a0 = bAddr0 + (unsigned)(g * 32);
                        asm volatile(
                            "ldmatrix.sync.aligned.m8n8.x4.shared.b16 {%0,%1,%2,%3}, [%4];"
                            : "=r"(bf[0]), "=r"(bf[1]), "=r"(bf[2]), "=r"(bf[3])
                            : "r"(a0));
                        asm volatile(
                            "ldmatrix.sync.aligned.m8n8.x4.shared.b16 {%0,%1,%2,%3}, [%4];"
                            : "=r"(bf[4]), "=r"(bf[5]), "=r"(bf[6]), "=r"(bf[7])
                            : "r"(a0 + 16u * C2_B_ROWB));
                    }
                    const int p = 2 * zloc + dz;
                    const int parity = dx & 1;
                    const int xh = xr + (dx >> 1);
                    const int yv = 4 * ypair + 2 * ysel + dy;
                    unsigned aAddr = actB
                        + (unsigned)(((p * 17 + yv) * 18 + parity * 9 + xh) * 48
                                     + hh * 16);
                    unsigned af[4];
                    asm volatile(
                        "ldmatrix.sync.aligned.m8n8.x4.shared.b16 {%0,%1,%2,%3}, [%4];"
                        : "=r"(af[0]), "=r"(af[1]), "=r"(af[2]), "=r"(af[3])
                        : "r"(aAddr));
#pragma unroll
                    for (int nt = 0; nt < 4; ++nt) {
                        float* c = &acc[nt * 4];
                        asm volatile(
                            "mma.sync.aligned.m16n8k16.row.col.f32.f16.f16.f32 "
                            "{%0,%1,%2,%3}, {%4,%5,%6,%7}, {%8,%9}, {%0,%1,%2,%3};"
                            : "+f"(c[0]), "+f"(c[1]), "+f"(c[2]), "+f"(c[3])
                            : "r"(af[0]), "r"(af[1]), "r"(af[2]), "r"(af[3]),
                              "r"(bf[nt * 2]), "r"(bf[nt * 2 + 1]));
                    }
                }

        __syncthreads();   // act dead -> stage may overwrite

        {
            const int row = lane >> 2, col2 = (lane & 3) * 2;
#pragma unroll
            for (int nt = 0; nt < 4; ++nt) {
                const int cb0 = nt * 8 + col2;
                *(float2*)&stage[row * 34 + cb0]       =
                    make_float2(acc[nt * 4 + 0], acc[nt * 4 + 1]);
                *(float2*)&stage[(row + 8) * 34 + cb0] =
                    make_float2(acc[nt * 4 + 2], acc[nt * 4 + 3]);
            }
            __syncwarp();
            {
                const int spq = lane & 15, half = lane >> 4;
                const int z = t2 * 2 + zloc;
                const int spg = z * 64 + ypair * 16 + spq;
                float o[16];
#pragma unroll
                for (int j = 0; j < 16; ++j)
                    o[j] = fmaxf(stage[spq * 34 + half * 16 + j] + sB2[half * 16 + j],
                                 0.0f);
                float4* dst = (float4*)&outp[spg * 32 + half * 16];
#pragma unroll
                for (int q = 0; q < 4; ++q) dst[q] = ((float4*)o)[q];
            }
        }
        __syncthreads();
    }
}

// ---------------------------------------------------------------------------
// Kernel 3: conv3 via mma.sync m16n8k16 + relu + mean-pool + FC.
// ---------------------------------------------------------------------------
#define C3_ACT_B   64800        // 9 planes x 9 y x 10 x-slots x 80B
#define C3_W_ROWB  592
#define C3_W_B     (64 * C3_W_ROWB)     // 37888
#define C3MM_SMEM  (C3_ACT_B + C3_W_B + 512)

__global__ __launch_bounds__(256) void conv3_mma_kernel(
    const float* __restrict__ b3,
    const float* __restrict__ Wfc,
    const float* __restrict__ bfc,
    float* __restrict__ out)
{
    extern __shared__ __align__(16) char sm3[];
    char*  sAct   = sm3;
    char*  sW     = sm3 + C3_ACT_B;
    float* sStage = (float*)sW;                    // alias after mma done
    float* sB3    = (float*)(sm3 + C3_ACT_B + C3_W_B);
    float* sPooled = sB3 + 64;

    const int e = blockIdx.x;
    const int t = threadIdx.x;
    const int w = t >> 5, lane = t & 31;

    if (t < 64) sB3[t] = b3[t];

    for (int i = t; i < C3_ACT_B / 4; i += 256) ((unsigned*)sAct)[i] = 0u;
    __syncthreads();
    {
        const float4* src = (const float4*)(g_c2 + (size_t)e * 16384);
        for (int i = t; i < 4096; i += 256) {
            int sp = i >> 3, part = i & 7;
            float4 v = src[sp * 8 + part];
            __half2 h0 = __floats2half2_rn(v.x, v.y);
            __half2 h1 = __floats2half2_rn(v.z, v.w);
            int x = sp & 7, y = (sp >> 3) & 7, z = sp >> 6;
            int va = z * 7200 + y * 800 + ((x & 1) * 5 + (x >> 1)) * 80 + part * 8;
            uint2 st;
            st.x = *(unsigned*)&h0;
            st.y = *(unsigned*)&h1;
            *(uint2*)(sAct + va) = st;
        }
    }

    const int mt = w & 3, nh = w >> 2;
    const int lx = lane & 3, ysub = (lane >> 2) & 1;
    const int ysel = (lane >> 3) & 1, hh = lane >> 4;
    const int ly = ysel * 2 + ysub;
    const unsigned actB = smem_u32(sAct);
    const unsigned wBs  = smem_u32(sW);
    const int bgrp = lane >> 3, brow = lane & 7;
    const unsigned bAddr0 = wBs + (unsigned)((nh * 32 + (bgrp >> 1) * 8 + brow) * C3_W_ROWB
                                             + (bgrp & 1) * 16);

    float acc[16];
#pragma unroll
    for (int q = 0; q < 16; ++q) acc[q] = 0.0f;

    const unsigned* w3u = (const unsigned*)g_w3h;   // [64][432] u32

    for (int c = 0; c < 3; ++c) {
        __syncthreads();
        for (int j = t; j < 64 * 144; j += 256) {
            int oc = j / 144, jj = j % 144;
            *(unsigned*)(sW + oc * C3_W_ROWB + jj * 4) = w3u[oc * 432 + c * 144 + jj];
        }
        __syncthreads();
#pragma unroll
        for (int gl = 0; gl < 18; ++gl) {
            const int g = c * 18 + gl;
            const int tap = g >> 1, ih = g & 1;
            const int dz = tap / 9, dyr = (tap % 9) / 3, dx = tap % 3;
            const int xp = 2 * lx + dx;
            unsigned aAddr = actB
                + (unsigned)((2 * mt + dz) * 7200 + (2 * ly + dyr) * 800
                             + ((xp & 1) * 5 + (xp >> 1)) * 80 + ih * 32 + hh * 16);
            unsigned af[4];
            asm volatile(
                "ldmatrix.sync.aligned.m8n8.x4.shared.b16 {%0,%1,%2,%3}, [%4];"
                : "=r"(af[0]), "=r"(af[1]), "=r"(af[2]), "=r"(af[3])
                : "r"(aAddr));
            unsigned bf[8];
            {
                unsigned a0 = bAddr0 + (unsigned)(gl * 32);
                asm volatile(
                    "ldmatrix.sync.aligned.m8n8.x4.shared.b16 {%0,%1,%2,%3}, [%4];"
                    : "=r"(bf[0]), "=r"(bf[1]), "=r"(bf[2]), "=r"(bf[3])
                    : "r"(a0));
                asm volatile(
                    "ldmatrix.sync.aligned.m8n8.x4.shared.b16 {%0,%1,%2,%3}, [%4];"
                    : "=r"(bf[4]), "=r"(bf[5]), "=r"(bf[6]), "=r"(bf[7])
                    : "r"(a0 + 16u * C3_W_ROWB));
            }
#pragma unroll
            for (int nt = 0; nt < 4; ++nt) {
                float* cc = &acc[nt * 4];
                asm volatile(
                    "mma.sync.aligned.m16n8k16.row.col.f32.f16.f16.f32 "
                    "{%0,%1,%2,%3}, {%4,%5,%6,%7}, {%8,%9}, {%0,%1,%2,%3};"
                    : "+f"(cc[0]), "+f"(cc[1]), "+f"(cc[2]), "+f"(cc[3])
                    : "r"(af[0]), "r"(af[1]), "r"(af[2]), "r"(af[3]),
                      "r"(bf[nt * 2]), "r"(bf[nt * 2 + 1]));
            }
        }
    }
    __syncthreads();   // weights dead -> stage may overwrite

    {
        const int row = lane >> 2, col2 = (lane & 3) * 2;
#pragma unroll
        for (int nt = 0; nt < 4; ++nt) {
            const int oc0 = nh * 32 + nt * 8 + col2;
            const int sp0 = mt * 16 + row;
            sStage[sp0 * 66 + oc0]
                = fmaxf(acc[nt * 4 + 0] + sB3[oc0], 0.0f);
            sStage[sp0 * 66 + oc0 + 1]
                = fmaxf(acc[nt * 4 + 1] + sB3[oc0 + 1], 0.0f);
            sStage[(sp0 + 8) * 66 + oc0]
                = fmaxf(acc[nt * 4 + 2] + sB3[oc0], 0.0f);
            sStage[(sp0 + 8) * 66 + oc0 + 1]
                = fmaxf(acc[nt * 4 + 3] + sB3[oc0 + 1], 0.0f);
        }
    }
    __syncthreads();
    if (t < 64) {
        float s = 0.0f;
#pragma unroll 8
        for (int sp = 0; sp < 64; ++sp) s += sStage[sp * 66 + t];
        sPooled[t] = s * (1.0f / 64.0f);
    }
    __syncthreads();
    if (t < 64) {
        float r = bfc[t];
#pragma unroll 8
        for (int ic = 0; ic < 64; ++ic)
            r += sPooled[ic] * __ldg(&Wfc[ic * 64 + t]);
        out[e * 64 + t] = r;
    }
}

// ---------------------------------------------------------------------------
extern "C" void kernel_launch(void* const* d_in, const int* in_sizes, int n_in,
                              void* d_out, int out_size)
{
    const float* data   = (const float*)d_in[0];
    const int*   clusts = (const int*)d_in[1];
    const void*  cmask  = d_in[2];
    const int*   eidx   = (const int*)d_in[3];
    const float* W1     = (const float*)d_in[4];
    const float* b1     = (const float*)d_in[5];
    const float* W2     = (const float*)d_in[6];
    const float* b2     = (const float*)d_in[7];
    const float* W3     = (const float*)d_in[8];
    const float* b3     = (const float*)d_in[9];
    const float* Wfc    = (const float*)d_in[10];
    const float* bfc    = (const float*)d_in[11];
    float*       out    = (float*)d_out;

    const int C = in_sizes[1] / NPT;   // 256
    const int E = in_sizes[3] / 2;     // 1024
    const int maskWords = in_sizes[2] / 4;

    cudaFuncSetAttribute(vox_acc_kernel,
        cudaFuncAttributeMaxDynamicSharedMemorySize, VOXA_SMEM);
    cudaFuncSetAttribute(conv2_mma_kernel,
        cudaFuncAttributeMaxDynamicSharedMemorySize, C2MM_SMEM);
    cudaFuncSetAttribute(conv3_mma_kernel,
        cudaFuncAttributeMaxDynamicSharedMemorySize, C3MM_SMEM);

    detect_kernel<<<1, 256>>>(eidx, (const unsigned int*)cmask, E, maskWords);
    wtrans_kernel<<<216, 256>>>(W2, W3);
    vox_tab_kernel<<<C, 256>>>(data, clusts, cmask);
    vox_acc_kernel<<<dim3(C, 4), 256, VOXA_SMEM>>>();
    conv1c_kernel<<<C * 4, 256>>>(W1);
    fuseact_kernel<<<E, 256>>>(eidx, b1, E, C);
    conv2_mma_kernel<<<E, 256, C2MM_SMEM>>>(b2);
    conv3_mma_kernel<<<E, 256, C3MM_SMEM>>>(b3, Wfc, bfc, out);
}

// round 15
// speedup vs baseline: 2.0991x; 1.0732x over previous
#include <cuda_runtime.h>
#include <cuda_bf16.h>
#include <cuda_fp16.h>

#define NCLUST 256
#define NPT    128
#define NEDGE  1024
#define VS     32
#define VOXN   (VS*VS*VS)   // 32768

typedef unsigned long long ull;

__device__ __forceinline__ ull pk2(float lo, float hi) {
    ull r; asm("mov.b64 %0, {%1,%2};" : "=l"(r) : "f"(lo), "f"(hi)); return r;
}
__device__ __forceinline__ void fma2(ull& d, ull a, ull b) {
    asm("fma.rn.f32x2 %0, %1, %2, %0;" : "+l"(d) : "l"(a), "l"(b));
}
__device__ __forceinline__ float2 upk2(ull v) {
    float2 r; asm("mov.b64 {%0,%1}, %2;" : "=f"(r.x), "=f"(r.y) : "l"(v)); return r;
}
__device__ __forceinline__ unsigned smem_u32(const void* p) {
    unsigned a;
    asm("{ .reg .u64 t; cvta.to.shared.u64 t, %1; cvt.u32.u64 %0, t; }" : "=r"(a) : "l"(p));
    return a;
}

// Scratch (device globals)
__device__ float  g_cvox[NCLUST * VOXN];             // 32 MB
__device__ __align__(16) __half g_c1h[NCLUST * 4096 * 16];  // 34 MB, [c][sp][ic] fp16
__device__ float  g_c2[NEDGE * 512 * 32];            // 67 MB, [e][sp][oc]
__device__ __align__(16) __half g_acth[NEDGE * 4096 * 16];  // 134 MB, [e][sp][ic] fp16
__device__ __align__(16) float g_ovx[NCLUST * NPT * VS];    // 4 MB
__device__ __align__(16) float g_ovy[NCLUST * NPT * VS];
__device__ __align__(16) float g_ovz[NCLUST * NPT * VS];
__device__ __align__(16) float g_swt[NCLUST * NPT];
__device__ __align__(16) __half g_w2h[32 * 448];     // W2 fp16 [oc][tap*16+ic]
__device__ __align__(16) __half g_w3h[64 * 864];     // W3 fp16 [oc][tap*32+ic]
__device__ int    g_eidx_is_i64;
__device__ int    g_mask_is_u8;

// ---------------------------------------------------------------------------
// Kernel D: dtype layout detection
// ---------------------------------------------------------------------------
__global__ void detect_kernel(const int* __restrict__ eidx_w,
                              const unsigned int* __restrict__ mask_w,
                              int E, int maskWords)
{
    __shared__ int oddNZ, bigW;
    if (threadIdx.x == 0) { oddNZ = 0; bigW = 0; }
    __syncthreads();
    for (int i = threadIdx.x; i < E; i += blockDim.x)
        if (eidx_w[2 * i + 1] != 0) atomicOr(&oddNZ, 1);
    for (int i = threadIdx.x; i < maskWords; i += blockDim.x)
        if (mask_w[i] > 1u) atomicOr(&bigW, 1);
    __syncthreads();
    if (threadIdx.x == 0) {
        g_eidx_is_i64 = (oddNZ == 0) ? 1 : 0;
        g_mask_is_u8  = bigW;
    }
}

// ---------------------------------------------------------------------------
// Kernel W: W2 -> fp16 [oc][448]; W3 -> fp16 [oc][tap*32+ic]
// ---------------------------------------------------------------------------
__global__ void wtrans_kernel(const float* __restrict__ W2,
                              const float* __restrict__ W3)
{
    int i = blockIdx.x * blockDim.x + threadIdx.x;
    if (i < 64 * 32 * 27) {
        int oc = i / (32 * 27), r = i % (32 * 27), ic = r / 27, tap = r % 27;
        g_w3h[oc * 864 + tap * 32 + ic] = __float2half(W3[i]);
    }
    if (i < 32 * 448) {
        int oc = i / 448, k = i % 448;
        float v = 0.0f;
        if (k < 432) {
            int tap = k >> 4, ic = k & 15;
            v = W2[(oc * 16 + ic) * 27 + tap];
        }
        g_w2h[i] = __float2half(v);
    }
}

// ---------------------------------------------------------------------------
// Kernel 0a: per-cluster reduction + overlap tables -> gmem
// ---------------------------------------------------------------------------
__global__ __launch_bounds__(256) void vox_tab_kernel(
    const float* __restrict__ data,
    const int* __restrict__ clusts,
    const void* __restrict__ cmask)
{
    __shared__ __align__(16) float spx[NPT], spy[NPT], spz[NPT];
    __shared__ __align__(16) float red[6 * NPT];

    const int c = blockIdx.x;
    const int t = threadIdx.x;
    const int mask_u8 = g_mask_is_u8;

    if (t < NPT) {
        int idx = clusts[c * NPT + t];
        int m;
        if (mask_u8) m = ((const unsigned char*)cmask)[c * NPT + t];
        else         m = ((const int*)cmask)[c * NPT + t];
        float x = data[idx * 5 + 0];
        float y = data[idx * 5 + 1];
        float z = data[idx * 5 + 2];
        float v = data[idx * 5 + 4];
        spx[t] = x; spy[t] = y; spz[t] = z;
        g_swt[c * NPT + t] = m ? v : 0.0f;
        red[0*NPT + t] = m ? x :  1e9f;
        red[1*NPT + t] = m ? y :  1e9f;
        red[2*NPT + t] = m ? z :  1e9f;
        red[3*NPT + t] = m ? x : -1e9f;
        red[4*NPT + t] = m ? y : -1e9f;
        red[5*NPT + t] = m ? z : -1e9f;
    }
    __syncthreads();
    for (int s = 64; s > 0; s >>= 1) {
        if (t < s) {
            red[0*NPT + t] = fminf(red[0*NPT + t], red[0*NPT + t + s]);
            red[1*NPT + t] = fminf(red[1*NPT + t], red[1*NPT + t + s]);
            red[2*NPT + t] = fminf(red[2*NPT + t], red[2*NPT + t + s]);
            red[3*NPT + t] = fmaxf(red[3*NPT + t], red[3*NPT + t + s]);
            red[4*NPT + t] = fmaxf(red[4*NPT + t], red[4*NPT + t + s]);
            red[5*NPT + t] = fmaxf(red[5*NPT + t], red[5*NPT + t + s]);
        }
        __syncthreads();
    }
    const float minx = red[0], miny = red[NPT], minz = red[2*NPT];
    const float rx = red[3*NPT] - minx;
    const float ry = red[4*NPT] - miny;
    const float rz = red[5*NPT] - minz;
    const float mr = fmaxf(rx, fmaxf(ry, rz)) + 1.0f;
    const float gs  = 1.0f / mr;
    const float rgs = mr;
    const float ns  = 1.0f / (float)VS;

    {
        int p    = t & (NPT - 1);
        int half = t >> 7;
        float vx = (spx[p] - minx - rx * 0.5f - 0.5f) * gs + 0.5f;
        float vy = (spy[p] - miny - ry * 0.5f - 0.5f) * gs + 0.5f;
        float vz = (spz[p] - minz - rz * 0.5f - 0.5f) * gs + 0.5f;
        for (int b = half * 16; b < half * 16 + 16; ++b) {
            float lo = (float)b * ns;
            float ox = fminf(vx + gs, lo + ns) - fmaxf(vx, lo);
            float oy = fminf(vy + gs, lo + ns) - fmaxf(vy, lo);
            float oz = fminf(vz + gs, lo + ns) - fmaxf(vz, lo);
            g_ovx[c * NPT * VS + p * VS + b] = fmaxf(ox, 0.0f) * rgs;
            g_ovy[c * NPT * VS + p * VS + b] = fmaxf(oy, 0.0f) * rgs;
            g_ovz[c * NPT * VS + p * VS + b] = fmaxf(oz, 0.0f) * rgs;
        }
    }
}

// ---------------------------------------------------------------------------
// Kernel 0b: accumulate (fma2-packed). grid (C, 4).
// ---------------------------------------------------------------------------
#define VOXA_SMEM ((3 * NPT * VS + NPT) * 4)   // 49664 B

__global__ __launch_bounds__(256) void vox_acc_kernel()
{
    extern __shared__ __align__(16) float dsmv[];
    float* ovy = dsmv;
    float* ovz = dsmv + NPT * VS;
    float* ovx = dsmv + 2 * NPT * VS;
    float* sw  = dsmv + 3 * NPT * VS;

    const int c = blockIdx.x;
    const int pass = blockIdx.y;
    const int t = threadIdx.x;

    {
        const float4* sy = (const float4*)(g_ovy + c * NPT * VS);
        const float4* sz = (const float4*)(g_ovz + c * NPT * VS);
        const float4* sx = (const float4*)(g_ovx + c * NPT * VS);
#pragma unroll
        for (int r = 0; r < 4; ++r) {
            int i = t + r * 256;
            ((float4*)ovy)[i] = sy[i];
            ((float4*)ovz)[i] = sz[i];
            ((float4*)ovx)[i] = sx[i];
        }
        if (t < NPT) sw[t] = g_swt[c * NPT + t];
    }
    __syncthreads();

    float* outp = g_cvox + (size_t)c * VOXN;
    {
        int jk = t + pass * 256;
        int j = jk >> 5, k = jk & 31;
        ull acc[16];
#pragma unroll
        for (int i = 0; i < 16; ++i) acc[i] = 0ULL;
        for (int p = 0; p < NPT; ++p) {
            float ty = sw[p] * ovy[p * VS + j];
            if (ty != 0.0f) {
                float tz = ty * ovz[p * VS + k];
                ull tz2 = pk2(tz, tz);
                const ulonglong2* ox2 = (const ulonglong2*)&ovx[p * VS];
#pragma unroll
                for (int i4 = 0; i4 < 8; ++i4) {
                    ulonglong2 o = ox2[i4];
                    fma2(acc[i4 * 2],     o.x, tz2);
                    fma2(acc[i4 * 2 + 1], o.y, tz2);
                }
            }
        }
#pragma unroll
        for (int i = 0; i < 16; ++i) {
            float2 p2 = upk2(acc[i]);
            outp[(2 * i)     * 1024 + jk] = p2.x;
            outp[(2 * i + 1) * 1024 + jk] = p2.y;
        }
    }
}

// ---------------------------------------------------------------------------
// Kernel 1: per-CLUSTER linear conv1, z-slab tiling. Output fp16 [sp][ic].
// ---------------------------------------------------------------------------
#define C1SD 36
#define C1PL (33 * C1SD)     // 1188
#define C1SZ (9 * C1PL)      // 10692 floats

__global__ __launch_bounds__(256, 2) void conv1c_kernel(
    const float* __restrict__ W1)
{
    __shared__ __align__(16) float s_in[C1SZ];
    __shared__ __align__(16) float s_w[27 * 16];

    const int c    = blockIdx.x >> 2;
    const int slab = blockIdx.x & 3;
    const int t = threadIdx.x;
    const float* __restrict__ A = g_cvox + (size_t)c * VOXN;

    for (int i = t; i < C1SZ; i += 256) s_in[i] = 0.0f;
    for (int i = t; i < 432; i += 256) {
        int oc = i / 27, tap = i % 27;
        s_w[tap * 16 + oc] = W1[i];
    }
    __syncthreads();

    const int z0 = slab * 8;
#pragma unroll
    for (int r = 0; r < 9; ++r) {
        int i4 = t + r * 256;
        int zz = i4 >> 8, j = i4 & 255;
        int gz = z0 + zz;
        if (gz < 32) {
            float4 v = *(const float4*)&A[gz * 1024 + j * 4];
            *(float4*)&s_in[zz * C1PL + (j >> 3) * C1SD + (j & 7) * 4] = v;
        }
    }
    __syncthreads();

    const int x = t & 15, y = t >> 4;

    ull acc[4][8];
#pragma unroll
    for (int q = 0; q < 4; ++q)
#pragma unroll
        for (int m = 0; m < 8; ++m) acc[q][m] = 0ULL;

#pragma unroll
    for (int dz = 0; dz < 3; ++dz)
#pragma unroll
        for (int dy = 0; dy < 3; ++dy) {
            float2 v01[4];
            float  v2s[4];
#pragma unroll
            for (int q = 0; q < 4; ++q) {
                const int o = (2 * q + dz) * C1PL + (2 * y + dy) * C1SD + 2 * x;
                v01[q] = *(const float2*)&s_in[o];
                v2s[q] = s_in[o + 2];
            }
#pragma unroll
            for (int dx = 0; dx < 3; ++dx) {
                const int tap = (dz * 3 + dy) * 3 + dx;
                const ulonglong2 w01 = *(const ulonglong2*)&s_w[tap * 16];
                const ulonglong2 w23 = *(const ulonglong2*)&s_w[tap * 16 + 4];
                const ulonglong2 w45 = *(const ulonglong2*)&s_w[tap * 16 + 8];
                const ulonglong2 w67 = *(const ulonglong2*)&s_w[tap * 16 + 12];
#pragma unroll
                for (int q = 0; q < 4; ++q) {
                    float v = (dx == 0) ? v01[q].x : (dx == 1) ? v01[q].y : v2s[q];
                    ull vv = pk2(v, v);
                    fma2(acc[q][0], vv, w01.x);
                    fma2(acc[q][1], vv, w01.y);
                    fma2(acc[q][2], vv, w23.x);
                    fma2(acc[q][3], vv, w23.y);
                    fma2(acc[q][4], vv, w45.x);
                    fma2(acc[q][5], vv, w45.y);
                    fma2(acc[q][6], vv, w67.x);
                    fma2(acc[q][7], vv, w67.y);
                }
            }
        }

    __half* outp = g_c1h + (size_t)c * 65536;
#pragma unroll
    for (int q = 0; q < 4; ++q) {
        const int oz = slab * 4 + q;
        const int sp = oz * 256 + y * 16 + x;
        unsigned hv[8];
#pragma unroll
        for (int m = 0; m < 8; ++m) {
            float2 p = upk2(acc[q][m]);
            __half2 h = __floats2half2_rn(p.x, p.y);
            hv[m] = *(unsigned*)&h;
        }
        uint4* o4 = (uint4*)(outp + sp * 16);
        o4[0] = make_uint4(hv[0], hv[1], hv[2], hv[3]);
        o4[1] = make_uint4(hv[4], hv[5], hv[6], hv[7]);
    }
}

// ---------------------------------------------------------------------------
// Kernel F: per-edge fused activation fp16: relu(f16A+f16B+b1) -> g_acth
// ---------------------------------------------------------------------------
__global__ __launch_bounds__(256) void fuseact_kernel(
    const int* __restrict__ eidx,
    const float* __restrict__ b1,
    int E, int C)
{
    const int e = blockIdx.x;
    const int t = threadIdx.x;

    int ca, cb;
    if (g_eidx_is_i64) { ca = eidx[2 * e]; cb = eidx[2 * (E + e)]; }
    else               { ca = eidx[e];     cb = eidx[E + e];       }
    ca = min(max(ca, 0), C - 1);
    cb = min(max(cb, 0), C - 1);

    const uint2* __restrict__ A2 = (const uint2*)(g_c1h + (size_t)ca * 65536);
    const uint2* __restrict__ B2 = (const uint2*)(g_c1h + (size_t)cb * 65536);
    uint2* __restrict__ dst = (uint2*)(g_acth + (size_t)e * 65536);

    float4 bb[4];
#pragma unroll
    for (int q = 0; q < 4; ++q) bb[q] = __ldg((const float4*)b1 + q);

#pragma unroll
    for (int r = 0; r < 64; ++r) {
        int i = t + r * 256;             // 0..16383, icq = i & 3
        uint2 ua = A2[i], ub = B2[i];
        float2 a0 = __half22float2(*(__half2*)&ua.x);
        float2 a1 = __half22float2(*(__half2*)&ua.y);
        float2 b0 = __half22float2(*(__half2*)&ub.x);
        float2 b1v = __half22float2(*(__half2*)&ub.y);
        float4 bi = bb[i & 3];
        __half2 h0 = __floats2half2_rn(fmaxf(a0.x + b0.x + bi.x, 0.0f),
                                       fmaxf(a0.y + b0.y + bi.y, 0.0f));
        __half2 h1 = __floats2half2_rn(fmaxf(a1.x + b1v.x + bi.z, 0.0f),
                                       fmaxf(a1.y + b1v.y + bi.w, 0.0f));
        uint2 st;
        st.x = *(unsigned*)&h0;
        st.y = *(unsigned*)&h1;
        dst[i] = st;
    }
}

// ---------------------------------------------------------------------------
// Kernel 2: conv2 via mma.sync m16n8k16. grid = E*2 (2 tiles per block).
// ---------------------------------------------------------------------------
#define C2_B_ROWB   912
#define C2_B_BYTES  (32 * C2_B_ROWB)           // 29184
#define C2_ACT_BYTES (5 * 17 * 18 * 48)        // 73440
#define C2MM_SMEM   (C2_B_BYTES + C2_ACT_BYTES + 256)

__global__ __launch_bounds__(256) void conv2_mma_kernel(
    const float* __restrict__ b2)
{
    extern __shared__ __align__(16) char sm2[];
    char*  sB     = sm2;
    char*  sAct   = sm2 + C2_B_BYTES;
    float* sStage = (float*)sAct;               // ALIAS: act dead when staging
    float* sB2    = (float*)(sm2 + C2_B_BYTES + C2_ACT_BYTES);

    const int e  = blockIdx.x >> 1;
    const int hb = blockIdx.x & 1;
    const int t = threadIdx.x;
    const int w = t >> 5, lane = t & 31;

    if (t < 32) sB2[t] = b2[t];

    {
        const unsigned* w2u = (const unsigned*)g_w2h;
        for (int j = t; j < 32 * 224; j += 256) {
            int row = j / 224, ku = j % 224;
            *(unsigned*)(sB + row * C2_B_ROWB + ku * 4) = w2u[j];
        }
    }
    __syncthreads();

    const uint4* __restrict__ actq = (const uint4*)(g_acth + (size_t)e * 65536);

    const int xr   = lane & 7;
    const int ysel = (lane >> 3) & 1;
    const int hh   = (lane >> 4) & 1;
    const int zloc = w & 1, ypair = w >> 1;
    const unsigned actB = smem_u32(sAct);
    const unsigned bBs  = smem_u32(sB);
    const int bgrp = lane >> 3, brow = lane & 7;
    const unsigned bAddr0 = bBs + (unsigned)(((bgrp >> 1) * 8 + brow) * C2_B_ROWB
                                             + (bgrp & 1) * 16);
    float* stage = sStage + w * (16 * 34);
    float* outp = g_c2 + (size_t)e * 16384;

    for (int t2 = 2 * hb; t2 < 2 * hb + 2; ++t2) {
        // ---- fill: pure fp16 copy
#pragma unroll
        for (int r = 0; r < 6; ++r) {
            int i = t + r * 256;
            if (i < 1445) {
                int p = i / 289, rem = i % 289, yy = rem / 17, xx = rem % 17;
                int zz = t2 * 4 + p;
                uint4 u0 = make_uint4(0u, 0u, 0u, 0u), u1 = u0;
                if (zz < 16 && yy < 16 && xx < 16) {
                    int sp = (zz * 16 + yy) * 16 + xx;
                    u0 = actq[sp * 2];
                    u1 = actq[sp * 2 + 1];
                }
                int voff = ((p * 17 + yy) * 18 + (xx & 1) * 9 + (xx >> 1)) * 48;
                *(uint4*)(sAct + voff)      = u0;
                *(uint4*)(sAct + voff + 16) = u1;
            }
        }
        __syncthreads();

        float acc[16];
#pragma unroll
        for (int q = 0; q < 16; ++q) acc[q] = 0.0f;

#pragma unroll
        for (int dz = 0; dz < 3; ++dz)
#pragma unroll
            for (int dy = 0; dy < 3; ++dy)
#pragma unroll
                for (int dx = 0; dx < 3; ++dx) {
                    const int g = (dz * 3 + dy) * 3 + dx;
                    unsigned bf[8];
                    {
                        unsigned a0 = bAddr0 + (unsigned)(g * 32);
                        asm volatile(
                            "ldmatrix.sync.aligned.m8n8.x4.shared.b16 {%0,%1,%2,%3}, [%4];"
                            : "=r"(bf[0]), "=r"(bf[1]), "=r"(bf[2]), "=r"(bf[3])
                            : "r"(a0));
                        asm volatile(
                            "ldmatrix.sync.aligned.m8n8.x4.shared.b16 {%0,%1,%2,%3}, [%4];"
                            : "=r"(bf[4]), "=r"(bf[5]), "=r"(bf[6]), "=r"(bf[7])
                            : "r"(a0 + 16u * C2_B_ROWB));
                    }
                    const int p = 2 * zloc + dz;
                    const int parity = dx & 1;
                    const int xh = xr + (dx >> 1);
                    const int yv = 4 * ypair + 2 * ysel + dy;
                    unsigned aAddr = actB
                        + (unsigned)(((p * 17 + yv) * 18 + parity * 9 + xh) * 48
                                     + hh * 16);
                    unsigned af[4];
                    asm volatile(
                        "ldmatrix.sync.aligned.m8n8.x4.shared.b16 {%0,%1,%2,%3}, [%4];"
                        : "=r"(af[0]), "=r"(af[1]), "=r"(af[2]), "=r"(af[3])
                        : "r"(aAddr));
#pragma unroll
                    for (int nt = 0; nt < 4; ++nt) {
                        float* c = &acc[nt * 4];
                        asm volatile(
                            "mma.sync.aligned.m16n8k16.row.col.f32.f16.f16.f32 "
                            "{%0,%1,%2,%3}, {%4,%5,%6,%7}, {%8,%9}, {%0,%1,%2,%3};"
                            : "+f"(c[0]), "+f"(c[1]), "+f"(c[2]), "+f"(c[3])
                            : "r"(af[0]), "r"(af[1]), "r"(af[2]), "r"(af[3]),
                              "r"(bf[nt * 2]), "r"(bf[nt * 2 + 1]));
                    }
                }

        __syncthreads();   // act dead -> stage may overwrite

        {
            const int row = lane >> 2, col2 = (lane & 3) * 2;
#pragma unroll
            for (int nt = 0; nt < 4; ++nt) {
                const int cb0 = nt * 8 + col2;
                *(float2*)&stage[row * 34 + cb0]       =
                    make_float2(acc[nt * 4 + 0], acc[nt * 4 + 1]);
                *(float2*)&stage[(row + 8) * 34 + cb0] =
                    make_float2(acc[nt * 4 + 2], acc[nt * 4 + 3]);
            }
            __syncwarp();
            {
                const int spq = lane & 15, half = lane >> 4;
                const int z = t2 * 2 + zloc;
                const int spg = z * 64 + ypair * 16 + spq;
                float o[16];
#pragma unroll
                for (int j = 0; j < 16; ++j)
                    o[j] = fmaxf(stage[spq * 34 + half * 16 + j] + sB2[half * 16 + j],
                                 0.0f);
                float4* dst = (float4*)&outp[spg * 32 + half * 16];
#pragma unroll
                for (int q = 0; q < 4; ++q) dst[q] = ((float4*)o)[q];
            }
        }
        __syncthreads();
    }
}

// ---------------------------------------------------------------------------
// Kernel 3: conv3 via mma.sync m16n8k16 + relu + mean-pool + FC.
// ---------------------------------------------------------------------------
#define C3_ACT_B   64800        // 9 planes x 9 y x 10 x-slots x 80B
#define C3_W_ROWB  592
#define C3_W_B     (64 * C3_W_ROWB)     // 37888
#define C3MM_SMEM  (C3_ACT_B + C3_W_B + 512)

__global__ __launch_bounds__(256) void conv3_mma_kernel(
    const float* __restrict__ b3,
    const float* __restrict__ Wfc,
    const float* __restrict__ bfc,
    float* __restrict__ out)
{
    extern __shared__ __align__(16) char sm3[];
    char*  sAct   = sm3;
    char*  sW     = sm3 + C3_ACT_B;
    float* sStage = (float*)sW;                    // alias after mma done
    float* sB3    = (float*)(sm3 + C3_ACT_B + C3_W_B);
    float* sPooled = sB3 + 64;

    const int e = blockIdx.x;
    const int t = threadIdx.x;
    const int w = t >> 5, lane = t & 31;

    if (t < 64) sB3[t] = b3[t];

    for (int i = t; i < C3_ACT_B / 4; i += 256) ((unsigned*)sAct)[i] = 0u;
    __syncthreads();
    {
        const float4* src = (const float4*)(g_c2 + (size_t)e * 16384);
        for (int i = t; i < 4096; i += 256) {
            int sp = i >> 3, part = i & 7;
            float4 v = src[sp * 8 + part];
            __half2 h0 = __floats2half2_rn(v.x, v.y);
            __half2 h1 = __floats2half2_rn(v.z, v.w);
            int x = sp & 7, y = (sp >> 3) & 7, z = sp >> 6;
            int va = z * 7200 + y * 800 + ((x & 1) * 5 + (x >> 1)) * 80 + part * 8;
            uint2 st;
            st.x = *(unsigned*)&h0;
            st.y = *(unsigned*)&h1;
            *(uint2*)(sAct + va) = st;
        }
    }

    const int mt = w & 3, nh = w >> 2;
    const int lx = lane & 3, ysub = (lane >> 2) & 1;
    const int ysel = (lane >> 3) & 1, hh = lane >> 4;
    const int ly = ysel * 2 + ysub;
    const unsigned actB = smem_u32(sAct);
    const unsigned wBs  = smem_u32(sW);
    const int bgrp = lane >> 3, brow = lane & 7;
    const unsigned bAddr0 = wBs + (unsigned)((nh * 32 + (bgrp >> 1) * 8 + brow) * C3_W_ROWB
                                             + (bgrp & 1) * 16);

    float acc[16];
#pragma unroll
    for (int q = 0; q < 16; ++q) acc[q] = 0.0f;

    const unsigned* w3u = (const unsigned*)g_w3h;   // [64][432] u32

    for (int c = 0; c < 3; ++c) {
        __syncthreads();
        for (int j = t; j < 64 * 144; j += 256) {
            int oc = j / 144, jj = j % 144;
            *(unsigned*)(sW + oc * C3_W_ROWB + jj * 4) = w3u[oc * 432 + c * 144 + jj];
        }
        __syncthreads();
#pragma unroll
        for (int gl = 0; gl < 18; ++gl) {
            const int g = c * 18 + gl;
            const int tap = g >> 1, ih = g & 1;
            const int dz = tap / 9, dyr = (tap % 9) / 3, dx = tap % 3;
            const int xp = 2 * lx + dx;
            unsigned aAddr = actB
                + (unsigned)((2 * mt + dz) * 7200 + (2 * ly + dyr) * 800
                             + ((xp & 1) * 5 + (xp >> 1)) * 80 + ih * 32 + hh * 16);
            unsigned af[4];
            asm volatile(
                "ldmatrix.sync.aligned.m8n8.x4.shared.b16 {%0,%1,%2,%3}, [%4];"
                : "=r"(af[0]), "=r"(af[1]), "=r"(af[2]), "=r"(af[3])
                : "r"(aAddr));
            unsigned bf[8];
            {
                unsigned a0 = bAddr0 + (unsigned)(gl * 32);
                asm volatile(
                    "ldmatrix.sync.aligned.m8n8.x4.shared.b16 {%0,%1,%2,%3}, [%4];"
                    : "=r"(bf[0]), "=r"(bf[1]), "=r"(bf[2]), "=r"(bf[3])
                    : "r"(a0));
                asm volatile(
                    "ldmatrix.sync.aligned.m8n8.x4.shared.b16 {%0,%1,%2,%3}, [%4];"
                    : "=r"(bf[4]), "=r"(bf[5]), "=r"(bf[6]), "=r"(bf[7])
                    : "r"(a0 + 16u * C3_W_ROWB));
            }
#pragma unroll
            for (int nt = 0; nt < 4; ++nt) {
                float* cc = &acc[nt * 4];
                asm volatile(
                    "mma.sync.aligned.m16n8k16.row.col.f32.f16.f16.f32 "
                    "{%0,%1,%2,%3}, {%4,%5,%6,%7}, {%8,%9}, {%0,%1,%2,%3};"
                    : "+f"(cc[0]), "+f"(cc[1]), "+f"(cc[2]), "+f"(cc[3])
                    : "r"(af[0]), "r"(af[1]), "r"(af[2]), "r"(af[3]),
                      "r"(bf[nt * 2]), "r"(bf[nt * 2 + 1]));
            }
        }
    }
    __syncthreads();   // weights dead -> stage may overwrite

    {
        const int row = lane >> 2, col2 = (lane & 3) * 2;
#pragma unroll
        for (int nt = 0; nt < 4; ++nt) {
            const int oc0 = nh * 32 + nt * 8 + col2;
            const int sp0 = mt * 16 + row;
            sStage[sp0 * 66 + oc0]
                = fmaxf(acc[nt * 4 + 0] + sB3[oc0], 0.0f);
            sStage[sp0 * 66 + oc0 + 1]
                = fmaxf(acc[nt * 4 + 1] + sB3[oc0 + 1], 0.0f);
            sStage[(sp0 + 8) * 66 + oc0]
                = fmaxf(acc[nt * 4 + 2] + sB3[oc0], 0.0f);
            sStage[(sp0 + 8) * 66 + oc0 + 1]
                = fmaxf(acc[nt * 4 + 3] + sB3[oc0 + 1], 0.0f);
        }
    }
    __syncthreads();
    if (t < 64) {
        float s = 0.0f;
#pragma unroll 8
        for (int sp = 0; sp < 64; ++sp) s += sStage[sp * 66 + t];
        sPooled[t] = s * (1.0f / 64.0f);
    }
    __syncthreads();
    if (t < 64) {
        float r = bfc[t];
#pragma unroll 8
        for (int ic = 0; ic < 64; ++ic)
            r += sPooled[ic] * __ldg(&Wfc[ic * 64 + t]);
        out[e * 64 + t] = r;
    }
}

// ---------------------------------------------------------------------------
extern "C" void kernel_launch(void* const* d_in, const int* in_sizes, int n_in,
                              void* d_out, int out_size)
{
    const float* data   = (const float*)d_in[0];
    const int*   clusts = (const int*)d_in[1];
    const void*  cmask  = d_in[2];
    const int*   eidx   = (const int*)d_in[3];
    const float* W1     = (const float*)d_in[4];
    const float* b1     = (const float*)d_in[5];
    const float* W2     = (const float*)d_in[6];
    const float* b2     = (const float*)d_in[7];
    const float* W3     = (const float*)d_in[8];
    const float* b3     = (const float*)d_in[9];
    const float* Wfc    = (const float*)d_in[10];
    const float* bfc    = (const float*)d_in[11];
    float*       out    = (float*)d_out;

    const int C = in_sizes[1] / NPT;   // 256
    const int E = in_sizes[3] / 2;     // 1024
    const int maskWords = in_sizes[2] / 4;

    cudaFuncSetAttribute(vox_acc_kernel,
        cudaFuncAttributeMaxDynamicSharedMemorySize, VOXA_SMEM);
    cudaFuncSetAttribute(conv2_mma_kernel,
        cudaFuncAttributeMaxDynamicSharedMemorySize, C2MM_SMEM);
    cudaFuncSetAttribute(conv3_mma_kernel,
        cudaFuncAttributeMaxDynamicSharedMemorySize, C3MM_SMEM);

    detect_kernel<<<1, 256>>>(eidx, (const unsigned int*)cmask, E, maskWords);
    wtrans_kernel<<<216, 256>>>(W2, W3);
    vox_tab_kernel<<<C, 256>>>(data, clusts, cmask);
    vox_acc_kernel<<<dim3(C, 4), 256, VOXA_SMEM>>>();
    conv1c_kernel<<<C * 4, 256>>>(W1);
    fuseact_kernel<<<E, 256>>>(eidx, b1, E, C);
    conv2_mma_kernel<<<E * 2, 256, C2MM_SMEM>>>(b2);
    conv3_mma_kernel<<<E, 256, C3MM_SMEM>>>(b3, Wfc, bfc, out);
}

// round 16
// speedup vs baseline: 2.6013x; 1.2393x over previous
#include <cuda_runtime.h>
#include <cuda_bf16.h>
#include <cuda_fp16.h>

#define NCLUST 256
#define NPT    128
#define NEDGE  1024
#define VS     32
#define VOXN   (VS*VS*VS)   // 32768

typedef unsigned long long ull;

__device__ __forceinline__ ull pk2(float lo, float hi) {
    ull r; asm("mov.b64 %0, {%1,%2};" : "=l"(r) : "f"(lo), "f"(hi)); return r;
}
__device__ __forceinline__ void fma2(ull& d, ull a, ull b) {
    asm("fma.rn.f32x2 %0, %1, %2, %0;" : "+l"(d) : "l"(a), "l"(b));
}
__device__ __forceinline__ float2 upk2(ull v) {
    float2 r; asm("mov.b64 {%0,%1}, %2;" : "=f"(r.x), "=f"(r.y) : "l"(v)); return r;
}
__device__ __forceinline__ unsigned smem_u32(const void* p) {
    unsigned a;
    asm("{ .reg .u64 t; cvta.to.shared.u64 t, %1; cvt.u32.u64 %0, t; }" : "=r"(a) : "l"(p));
    return a;
}

// Scratch (device globals)
__device__ float  g_cvox[NCLUST * VOXN];             // 32 MB
__device__ __align__(16) __half g_c1h[NCLUST * 4096 * 16];  // 34 MB, [c][sp][ic] fp16
__device__ __align__(16) __half g_c2h[NEDGE * 512 * 32];    // 34 MB, [e][sp][oc] fp16
__device__ __align__(16) float g_ovx[NCLUST * NPT * VS];    // 4 MB
__device__ __align__(16) float g_ovy[NCLUST * NPT * VS];
__device__ __align__(16) float g_ovz[NCLUST * NPT * VS];
__device__ __align__(16) float g_swt[NCLUST * NPT];
__device__ __align__(16) __half g_w2h[32 * 448];     // W2 fp16 [oc][tap*16+ic]
__device__ __align__(16) __half g_w3h[64 * 864];     // W3 fp16 [oc][tap*32+ic]
__device__ int    g_eidx_is_i64;
__device__ int    g_mask_is_u8;

// ---------------------------------------------------------------------------
// Kernel D: dtype layout detection
// ---------------------------------------------------------------------------
__global__ void detect_kernel(const int* __restrict__ eidx_w,
                              const unsigned int* __restrict__ mask_w,
                              int E, int maskWords)
{
    __shared__ int oddNZ, bigW;
    if (threadIdx.x == 0) { oddNZ = 0; bigW = 0; }
    __syncthreads();
    for (int i = threadIdx.x; i < E; i += blockDim.x)
        if (eidx_w[2 * i + 1] != 0) atomicOr(&oddNZ, 1);
    for (int i = threadIdx.x; i < maskWords; i += blockDim.x)
        if (mask_w[i] > 1u) atomicOr(&bigW, 1);
    __syncthreads();
    if (threadIdx.x == 0) {
        g_eidx_is_i64 = (oddNZ == 0) ? 1 : 0;
        g_mask_is_u8  = bigW;
    }
}

// ---------------------------------------------------------------------------
// Kernel W: W2 -> fp16 [oc][448]; W3 -> fp16 [oc][tap*32+ic]
// ---------------------------------------------------------------------------
__global__ void wtrans_kernel(const float* __restrict__ W2,
                              const float* __restrict__ W3)
{
    int i = blockIdx.x * blockDim.x + threadIdx.x;
    if (i < 64 * 32 * 27) {
        int oc = i / (32 * 27), r = i % (32 * 27), ic = r / 27, tap = r % 27;
        g_w3h[oc * 864 + tap * 32 + ic] = __float2half(W3[i]);
    }
    if (i < 32 * 448) {
        int oc = i / 448, k = i % 448;
        float v = 0.0f;
        if (k < 432) {
            int tap = k >> 4, ic = k & 15;
            v = W2[(oc * 16 + ic) * 27 + tap];
        }
        g_w2h[i] = __float2half(v);
    }
}

// ---------------------------------------------------------------------------
// Kernel 0a: per-cluster reduction + overlap tables -> gmem
// ---------------------------------------------------------------------------
__global__ __launch_bounds__(256) void vox_tab_kernel(
    const float* __restrict__ data,
    const int* __restrict__ clusts,
    const void* __restrict__ cmask)
{
    __shared__ __align__(16) float spx[NPT], spy[NPT], spz[NPT];
    __shared__ __align__(16) float red[6 * NPT];

    const int c = blockIdx.x;
    const int t = threadIdx.x;
    const int mask_u8 = g_mask_is_u8;

    if (t < NPT) {
        int idx = clusts[c * NPT + t];
        int m;
        if (mask_u8) m = ((const unsigned char*)cmask)[c * NPT + t];
        else         m = ((const int*)cmask)[c * NPT + t];
        float x = data[idx * 5 + 0];
        float y = data[idx * 5 + 1];
        float z = data[idx * 5 + 2];
        float v = data[idx * 5 + 4];
        spx[t] = x; spy[t] = y; spz[t] = z;
        g_swt[c * NPT + t] = m ? v : 0.0f;
        red[0*NPT + t] = m ? x :  1e9f;
        red[1*NPT + t] = m ? y :  1e9f;
        red[2*NPT + t] = m ? z :  1e9f;
        red[3*NPT + t] = m ? x : -1e9f;
        red[4*NPT + t] = m ? y : -1e9f;
        red[5*NPT + t] = m ? z : -1e9f;
    }
    __syncthreads();
    for (int s = 64; s > 0; s >>= 1) {
        if (t < s) {
            red[0*NPT + t] = fminf(red[0*NPT + t], red[0*NPT + t + s]);
            red[1*NPT + t] = fminf(red[1*NPT + t], red[1*NPT + t + s]);
            red[2*NPT + t] = fminf(red[2*NPT + t], red[2*NPT + t + s]);
            red[3*NPT + t] = fmaxf(red[3*NPT + t], red[3*NPT + t + s]);
            red[4*NPT + t] = fmaxf(red[4*NPT + t], red[4*NPT + t + s]);
            red[5*NPT + t] = fmaxf(red[5*NPT + t], red[5*NPT + t + s]);
        }
        __syncthreads();
    }
    const float minx = red[0], miny = red[NPT], minz = red[2*NPT];
    const float rx = red[3*NPT] - minx;
    const float ry = red[4*NPT] - miny;
    const float rz = red[5*NPT] - minz;
    const float mr = fmaxf(rx, fmaxf(ry, rz)) + 1.0f;
    const float gs  = 1.0f / mr;
    const float rgs = mr;
    const float ns  = 1.0f / (float)VS;

    {
        int p    = t & (NPT - 1);
        int half = t >> 7;
        float vx = (spx[p] - minx - rx * 0.5f - 0.5f) * gs + 0.5f;
        float vy = (spy[p] - miny - ry * 0.5f - 0.5f) * gs + 0.5f;
        float vz = (spz[p] - minz - rz * 0.5f - 0.5f) * gs + 0.5f;
        for (int b = half * 16; b < half * 16 + 16; ++b) {
            float lo = (float)b * ns;
            float ox = fminf(vx + gs, lo + ns) - fmaxf(vx, lo);
            float oy = fminf(vy + gs, lo + ns) - fmaxf(vy, lo);
            float oz = fminf(vz + gs, lo + ns) - fmaxf(vz, lo);
            g_ovx[c * NPT * VS + p * VS + b] = fmaxf(ox, 0.0f) * rgs;
            g_ovy[c * NPT * VS + p * VS + b] = fmaxf(oy, 0.0f) * rgs;
            g_ovz[c * NPT * VS + p * VS + b] = fmaxf(oz, 0.0f) * rgs;
        }
    }
}

// ---------------------------------------------------------------------------
// Kernel 0b: accumulate (fma2-packed). grid (C, 4).
// ---------------------------------------------------------------------------
#define VOXA_SMEM ((3 * NPT * VS + NPT) * 4)   // 49664 B

__global__ __launch_bounds__(256) void vox_acc_kernel()
{
    extern __shared__ __align__(16) float dsmv[];
    float* ovy = dsmv;
    float* ovz = dsmv + NPT * VS;
    float* ovx = dsmv + 2 * NPT * VS;
    float* sw  = dsmv + 3 * NPT * VS;

    const int c = blockIdx.x;
    const int pass = blockIdx.y;
    const int t = threadIdx.x;

    {
        const float4* sy = (const float4*)(g_ovy + c * NPT * VS);
        const float4* sz = (const float4*)(g_ovz + c * NPT * VS);
        const float4* sx = (const float4*)(g_ovx + c * NPT * VS);
#pragma unroll
        for (int r = 0; r < 4; ++r) {
            int i = t + r * 256;
            ((float4*)ovy)[i] = sy[i];
            ((float4*)ovz)[i] = sz[i];
            ((float4*)ovx)[i] = sx[i];
        }
        if (t < NPT) sw[t] = g_swt[c * NPT + t];
    }
    __syncthreads();

    float* outp = g_cvox + (size_t)c * VOXN;
    {
        int jk = t + pass * 256;
        int j = jk >> 5, k = jk & 31;
        ull acc[16];
#pragma unroll
        for (int i = 0; i < 16; ++i) acc[i] = 0ULL;
        for (int p = 0; p < NPT; ++p) {
            float ty = sw[p] * ovy[p * VS + j];
            if (ty != 0.0f) {
                float tz = ty * ovz[p * VS + k];
                ull tz2 = pk2(tz, tz);
                const ulonglong2* ox2 = (const ulonglong2*)&ovx[p * VS];
#pragma unroll
                for (int i4 = 0; i4 < 8; ++i4) {
                    ulonglong2 o = ox2[i4];
                    fma2(acc[i4 * 2],     o.x, tz2);
                    fma2(acc[i4 * 2 + 1], o.y, tz2);
                }
            }
        }
#pragma unroll
        for (int i = 0; i < 16; ++i) {
            float2 p2 = upk2(acc[i]);
            outp[(2 * i)     * 1024 + jk] = p2.x;
            outp[(2 * i + 1) * 1024 + jk] = p2.y;
        }
    }
}

// ---------------------------------------------------------------------------
// Kernel 1: per-CLUSTER linear conv1, z-slab tiling. Output fp16 [sp][ic].
// ---------------------------------------------------------------------------
#define C1SD 36
#define C1PL (33 * C1SD)     // 1188
#define C1SZ (9 * C1PL)      // 10692 floats

__global__ __launch_bounds__(256, 2) void conv1c_kernel(
    const float* __restrict__ W1)
{
    __shared__ __align__(16) float s_in[C1SZ];
    __shared__ __align__(16) float s_w[27 * 16];

    const int c    = blockIdx.x >> 2;
    const int slab = blockIdx.x & 3;
    const int t = threadIdx.x;
    const float* __restrict__ A = g_cvox + (size_t)c * VOXN;

    for (int i = t; i < C1SZ; i += 256) s_in[i] = 0.0f;
    for (int i = t; i < 432; i += 256) {
        int oc = i / 27, tap = i % 27;
        s_w[tap * 16 + oc] = W1[i];
    }
    __syncthreads();

    const int z0 = slab * 8;
#pragma unroll
    for (int r = 0; r < 9; ++r) {
        int i4 = t + r * 256;
        int zz = i4 >> 8, j = i4 & 255;
        int gz = z0 + zz;
        if (gz < 32) {
            float4 v = *(const float4*)&A[gz * 1024 + j * 4];
            *(float4*)&s_in[zz * C1PL + (j >> 3) * C1SD + (j & 7) * 4] = v;
        }
    }
    __syncthreads();

    const int x = t & 15, y = t >> 4;

    ull acc[4][8];
#pragma unroll
    for (int q = 0; q < 4; ++q)
#pragma unroll
        for (int m = 0; m < 8; ++m) acc[q][m] = 0ULL;

#pragma unroll
    for (int dz = 0; dz < 3; ++dz)
#pragma unroll
        for (int dy = 0; dy < 3; ++dy) {
            float2 v01[4];
            float  v2s[4];
#pragma unroll
            for (int q = 0; q < 4; ++q) {
                const int o = (2 * q + dz) * C1PL + (2 * y + dy) * C1SD + 2 * x;
                v01[q] = *(const float2*)&s_in[o];
                v2s[q] = s_in[o + 2];
            }
#pragma unroll
            for (int dx = 0; dx < 3; ++dx) {
                const int tap = (dz * 3 + dy) * 3 + dx;
                const ulonglong2 w01 = *(const ulonglong2*)&s_w[tap * 16];
                const ulonglong2 w23 = *(const ulonglong2*)&s_w[tap * 16 + 4];
                const ulonglong2 w45 = *(const ulonglong2*)&s_w[tap * 16 + 8];
                const ulonglong2 w67 = *(const ulonglong2*)&s_w[tap * 16 + 12];
#pragma unroll
                for (int q = 0; q < 4; ++q) {
                    float v = (dx == 0) ? v01[q].x : (dx == 1) ? v01[q].y : v2s[q];
                    ull vv = pk2(v, v);
                    fma2(acc[q][0], vv, w01.x);
                    fma2(acc[q][1], vv, w01.y);
                    fma2(acc[q][2], vv, w23.x);
                    fma2(acc[q][3], vv, w23.y);
                    fma2(acc[q][4], vv, w45.x);
                    fma2(acc[q][5], vv, w45.y);
                    fma2(acc[q][6], vv, w67.x);
                    fma2(acc[q][7], vv, w67.y);
                }
            }
        }

    __half* outp = g_c1h + (size_t)c * 65536;
#pragma unroll
    for (int q = 0; q < 4; ++q) {
        const int oz = slab * 4 + q;
        const int sp = oz * 256 + y * 16 + x;
        unsigned hv[8];
#pragma unroll
        for (int m = 0; m < 8; ++m) {
            float2 p = upk2(acc[q][m]);
            __half2 h = __floats2half2_rn(p.x, p.y);
            hv[m] = *(unsigned*)&h;
        }
        uint4* o4 = (uint4*)(outp + sp * 16);
        o4[0] = make_uint4(hv[0], hv[1], hv[2], hv[3]);
        o4[1] = make_uint4(hv[4], hv[5], hv[6], hv[7]);
    }
}

// ---------------------------------------------------------------------------
// Kernel 2: conv2 via mma.sync m16n8k16. grid = E*2.
// Fill computes relu(A+B+b1) inline from fp16 g_c1h (fuseact folded in).
// ---------------------------------------------------------------------------
#define C2_B_ROWB   912
#define C2_B_BYTES  (32 * C2_B_ROWB)           // 29184
#define C2_ACT_BYTES (5 * 17 * 18 * 48)        // 73440
#define C2MM_SMEM   (C2_B_BYTES + C2_ACT_BYTES + 256)

__global__ __launch_bounds__(256) void conv2_mma_kernel(
    const int* __restrict__ eidx,
    const float* __restrict__ b1,
    const float* __restrict__ b2,
    int E, int C)
{
    extern __shared__ __align__(16) char sm2[];
    char*  sB     = sm2;
    char*  sAct   = sm2 + C2_B_BYTES;
    float* sStage = (float*)sAct;               // ALIAS: act dead when staging
    float* sB2    = (float*)(sm2 + C2_B_BYTES + C2_ACT_BYTES);

    const int e  = blockIdx.x >> 1;
    const int hb = blockIdx.x & 1;
    const int t = threadIdx.x;
    const int w = t >> 5, lane = t & 31;

    int ca, cb;
    if (g_eidx_is_i64) { ca = eidx[2 * e]; cb = eidx[2 * (E + e)]; }
    else               { ca = eidx[e];     cb = eidx[E + e];       }
    ca = min(max(ca, 0), C - 1);
    cb = min(max(cb, 0), C - 1);

    if (t < 32) sB2[t] = b2[t];

    {
        const unsigned* w2u = (const unsigned*)g_w2h;
        for (int j = t; j < 32 * 224; j += 256) {
            int row = j / 224, ku = j % 224;
            *(unsigned*)(sB + row * C2_B_ROWB + ku * 4) = w2u[j];
        }
    }
    __syncthreads();

    const uint4* __restrict__ A4 = (const uint4*)(g_c1h + (size_t)ca * 65536);
    const uint4* __restrict__ B4 = (const uint4*)(g_c1h + (size_t)cb * 65536);

    float bf[16];
#pragma unroll
    for (int q = 0; q < 4; ++q) {
        float4 b4 = __ldg((const float4*)b1 + q);
        bf[4 * q] = b4.x; bf[4 * q + 1] = b4.y;
        bf[4 * q + 2] = b4.z; bf[4 * q + 3] = b4.w;
    }

    const int xr   = lane & 7;
    const int ysel = (lane >> 3) & 1;
    const int hh   = (lane >> 4) & 1;
    const int zloc = w & 1, ypair = w >> 1;
    const unsigned actB = smem_u32(sAct);
    const unsigned bBs  = smem_u32(sB);
    const int bgrp = lane >> 3, brow = lane & 7;
    const unsigned bAddr0 = bBs + (unsigned)(((bgrp >> 1) * 8 + brow) * C2_B_ROWB
                                             + (bgrp & 1) * 16);
    float* stage = sStage + w * (16 * 34);
    __half* outp = g_c2h + (size_t)e * 16384;

    for (int t2 = 2 * hb; t2 < 2 * hb + 2; ++t2) {
        // ---- fill: relu(A+B+b1) fp16 inline
#pragma unroll
        for (int r = 0; r < 6; ++r) {
            int i = t + r * 256;
            if (i < 1445) {
                int p = i / 289, rem = i % 289, yy = rem / 17, xx = rem % 17;
                int zz = t2 * 4 + p;
                uint4 u0 = make_uint4(0u, 0u, 0u, 0u), u1 = u0;
                if (zz < 16 && yy < 16 && xx < 16) {
                    int sp = (zz * 16 + yy) * 16 + xx;
                    unsigned ua[8], ub[8], hv[8];
                    *(uint4*)ua       = A4[sp * 2];
                    *(uint4*)(ua + 4) = A4[sp * 2 + 1];
                    *(uint4*)ub       = B4[sp * 2];
                    *(uint4*)(ub + 4) = B4[sp * 2 + 1];
#pragma unroll
                    for (int q = 0; q < 8; ++q) {
                        float2 fa = __half22float2(*(__half2*)&ua[q]);
                        float2 fb = __half22float2(*(__half2*)&ub[q]);
                        __half2 h = __floats2half2_rn(
                            fmaxf(fa.x + fb.x + bf[2 * q], 0.0f),
                            fmaxf(fa.y + fb.y + bf[2 * q + 1], 0.0f));
                        hv[q] = *(unsigned*)&h;
                    }
                    u0 = make_uint4(hv[0], hv[1], hv[2], hv[3]);
                    u1 = make_uint4(hv[4], hv[5], hv[6], hv[7]);
                }
                int voff = ((p * 17 + yy) * 18 + (xx & 1) * 9 + (xx >> 1)) * 48;
                *(uint4*)(sAct + voff)      = u0;
                *(uint4*)(sAct + voff + 16) = u1;
            }
        }
        __syncthreads();

        float acc[16];
#pragma unroll
        for (int q = 0; q < 16; ++q) acc[q] = 0.0f;

#pragma unroll
        for (int dz = 0; dz < 3; ++dz)
#pragma unroll
            for (int dy = 0; dy < 3; ++dy)
#pragma unroll
                for (int dx = 0; dx < 3; ++dx) {
                    const int g = (dz * 3 + dy) * 3 + dx;
                    unsigned bfr[8];
                    {
                        unsigned a0 = bAddr0 + (unsigned)(g * 32);
                        asm volatile(
                            "ldmatrix.sync.aligned.m8n8.x4.shared.b16 {%0,%1,%2,%3}, [%4];"
                            : "=r"(bfr[0]), "=r"(bfr[1]), "=r"(bfr[2]), "=r"(bfr[3])
                            : "r"(a0));
                        asm volatile(
                            "ldmatrix.sync.aligned.m8n8.x4.shared.b16 {%0,%1,%2,%3}, [%4];"
                            : "=r"(bfr[4]), "=r"(bfr[5]), "=r"(bfr[6]), "=r"(bfr[7])
                            : "r"(a0 + 16u * C2_B_ROWB));
                    }
                    const int p = 2 * zloc + dz;
                    const int parity = dx & 1;
                    const int xh = xr + (dx >> 1);
                    const int yv = 4 * ypair + 2 * ysel + dy;
                    unsigned aAddr = actB
                        + (unsigned)(((p * 17 + yv) * 18 + parity * 9 + xh) * 48
                                     + hh * 16);
                    unsigned af[4];
                    asm volatile(
                        "ldmatrix.sync.aligned.m8n8.x4.shared.b16 {%0,%1,%2,%3}, [%4];"
                        : "=r"(af[0]), "=r"(af[1]), "=r"(af[2]), "=r"(af[3])
                        : "r"(aAddr));
#pragma unroll
                    for (int nt = 0; nt < 4; ++nt) {
                        float* c = &acc[nt * 4];
                        asm volatile(
                            "mma.sync.aligned.m16n8k16.row.col.f32.f16.f16.f32 "
                            "{%0,%1,%2,%3}, {%4,%5,%6,%7}, {%8,%9}, {%0,%1,%2,%3};"
                            : "+f"(c[0]), "+f"(c[1]), "+f"(c[2]), "+f"(c[3])
                            : "r"(af[0]), "r"(af[1]), "r"(af[2]), "r"(af[3]),
                              "r"(bfr[nt * 2]), "r"(bfr[nt * 2 + 1]));
                    }
                }

        __syncthreads();   // act dead -> stage may overwrite

        {
            const int row = lane >> 2, col2 = (lane & 3) * 2;
#pragma unroll
            for (int nt = 0; nt < 4; ++nt) {
                const int cb0 = nt * 8 + col2;
                *(float2*)&stage[row * 34 + cb0]       =
                    make_float2(acc[nt * 4 + 0], acc[nt * 4 + 1]);
                *(float2*)&stage[(row + 8) * 34 + cb0] =
                    make_float2(acc[nt * 4 + 2], acc[nt * 4 + 3]);
            }
            __syncwarp();
            {
                const int spq = lane & 15, half = lane >> 4;
                const int z = t2 * 2 + zloc;
                const int spg = z * 64 + ypair * 16 + spq;
                unsigned hv[8];
#pragma unroll
                for (int j = 0; j < 8; ++j) {
                    float lo = fmaxf(stage[spq * 34 + half * 16 + 2 * j]
                                     + sB2[half * 16 + 2 * j], 0.0f);
                    float hi = fmaxf(stage[spq * 34 + half * 16 + 2 * j + 1]
                                     + sB2[half * 16 + 2 * j + 1], 0.0f);
                    __half2 h = __floats2half2_rn(lo, hi);
                    hv[j] = *(unsigned*)&h;
                }
                uint4* dst = (uint4*)&outp[spg * 32 + half * 16];
                dst[0] = make_uint4(hv[0], hv[1], hv[2], hv[3]);
                dst[1] = make_uint4(hv[4], hv[5], hv[6], hv[7]);
            }
        }
        __syncthreads();
    }
}

// ---------------------------------------------------------------------------
// Kernel 3: conv3 via mma.sync m16n8k16 + relu + mean-pool + FC.
// Fill = pure fp16 copy from g_c2h.
// ---------------------------------------------------------------------------
#define C3_ACT_B   64800        // 9 planes x 9 y x 10 x-slots x 80B
#define C3_W_ROWB  592
#define C3_W_B     (64 * C3_W_ROWB)     // 37888
#define C3MM_SMEM  (C3_ACT_B + C3_W_B + 512)

__global__ __launch_bounds__(256) void conv3_mma_kernel(
    const float* __restrict__ b3,
    const float* __restrict__ Wfc,
    const float* __restrict__ bfc,
    float* __restrict__ out)
{
    extern __shared__ __align__(16) char sm3[];
    char*  sAct   = sm3;
    char*  sW     = sm3 + C3_ACT_B;
    float* sStage = (float*)sW;                    // alias after mma done
    float* sB3    = (float*)(sm3 + C3_ACT_B + C3_W_B);
    float* sPooled = sB3 + 64;

    const int e = blockIdx.x;
    const int t = threadIdx.x;
    const int w = t >> 5, lane = t & 31;

    if (t < 64) sB3[t] = b3[t];

    for (int i = t; i < C3_ACT_B / 4; i += 256) ((unsigned*)sAct)[i] = 0u;
    __syncthreads();
    {
        const uint4* src = (const uint4*)(g_c2h + (size_t)e * 16384);   // 2048
#pragma unroll
        for (int r = 0; r < 8; ++r) {
            int i = t + r * 256;
            int sp = i >> 2, part = i & 3;
            uint4 v = src[i];
            int x = sp & 7, y = (sp >> 3) & 7, z = sp >> 6;
            int va = z * 7200 + y * 800 + ((x & 1) * 5 + (x >> 1)) * 80 + part * 16;
            *(uint4*)(sAct + va) = v;
        }
    }

    const int mt = w & 3, nh = w >> 2;
    const int lx = lane & 3, ysub = (lane >> 2) & 1;
    const int ysel = (lane >> 3) & 1, hh = lane >> 4;
    const int ly = ysel * 2 + ysub;
    const unsigned actB = smem_u32(sAct);
    const unsigned wBs  = smem_u32(sW);
    const int bgrp = lane >> 3, brow = lane & 7;
    const unsigned bAddr0 = wBs + (unsigned)((nh * 32 + (bgrp >> 1) * 8 + brow) * C3_W_ROWB
                                             + (bgrp & 1) * 16);

    float acc[16];
#pragma unroll
    for (int q = 0; q < 16; ++q) acc[q] = 0.0f;

    const unsigned* w3u = (const unsigned*)g_w3h;   // [64][432] u32

    for (int c = 0; c < 3; ++c) {
        __syncthreads();
        for (int j = t; j < 64 * 144; j += 256) {
            int oc = j / 144, jj = j % 144;
            *(unsigned*)(sW + oc * C3_W_ROWB + jj * 4) = w3u[oc * 432 + c * 144 + jj];
        }
        __syncthreads();
#pragma unroll
        for (int gl = 0; gl < 18; ++gl) {
            const int g = c * 18 + gl;
            const int tap = g >> 1, ih = g & 1;
            const int dz = tap / 9, dyr = (tap % 9) / 3, dx = tap % 3;
            const int xp = 2 * lx + dx;
            unsigned aAddr = actB
                + (unsigned)((2 * mt + dz) * 7200 + (2 * ly + dyr) * 800
                             + ((xp & 1) * 5 + (xp >> 1)) * 80 + ih * 32 + hh * 16);
            unsigned af[4];
            asm volatile(
                "ldmatrix.sync.aligned.m8n8.x4.shared.b16 {%0,%1,%2,%3}, [%4];"
                : "=r"(af[0]), "=r"(af[1]), "=r"(af[2]), "=r"(af[3])
                : "r"(aAddr));
            unsigned bfr[8];
            {
                unsigned a0 = bAddr0 + (unsigned)(gl * 32);
                asm volatile(
                    "ldmatrix.sync.aligned.m8n8.x4.shared.b16 {%0,%1,%2,%3}, [%4];"
                    : "=r"(bfr[0]), "=r"(bfr[1]), "=r"(bfr[2]), "=r"(bfr[3])
                    : "r"(a0));
                asm volatile(
                    "ldmatrix.sync.aligned.m8n8.x4.shared.b16 {%0,%1,%2,%3}, [%4];"
                    : "=r"(bfr[4]), "=r"(bfr[5]), "=r"(bfr[6]), "=r"(bfr[7])
                    : "r"(a0 + 16u * C3_W_ROWB));
            }
#pragma unroll
            for (int nt = 0; nt < 4; ++nt) {
                float* cc = &acc[nt * 4];
                asm volatile(
                    "mma.sync.aligned.m16n8k16.row.col.f32.f16.f16.f32 "
                    "{%0,%1,%2,%3}, {%4,%5,%6,%7}, {%8,%9}, {%0,%1,%2,%3};"
                    : "+f"(cc[0]), "+f"(cc[1]), "+f"(cc[2]), "+f"(cc[3])
                    : "r"(af[0]), "r"(af[1]), "r"(af[2]), "r"(af[3]),
                      "r"(bfr[nt * 2]), "r"(bfr[nt * 2 + 1]));
            }
        }
    }
    __syncthreads();   // weights dead -> stage may overwrite

    {
        const int row = lane >> 2, col2 = (lane & 3) * 2;
#pragma unroll
        for (int nt = 0; nt < 4; ++nt) {
            const int oc0 = nh * 32 + nt * 8 + col2;
            const int sp0 = mt * 16 + row;
            sStage[sp0 * 66 + oc0]
                = fmaxf(acc[nt * 4 + 0] + sB3[oc0], 0.0f);
            sStage[sp0 * 66 + oc0 + 1]
                = fmaxf(acc[nt * 4 + 1] + sB3[oc0 + 1], 0.0f);
            sStage[(sp0 + 8) * 66 + oc0]
                = fmaxf(acc[nt * 4 + 2] + sB3[oc0], 0.0f);
            sStage[(sp0 + 8) * 66 + oc0 + 1]
                = fmaxf(acc[nt * 4 + 3] + sB3[oc0 + 1], 0.0f);
        }
    }
    __syncthreads();
    if (t < 64) {
        float s = 0.0f;
#pragma unroll 8
        for (int sp = 0; sp < 64; ++sp) s += sStage[sp * 66 + t];
        sPooled[t] = s * (1.0f / 64.0f);
    }
    __syncthreads();
    if (t < 64) {
        float r = bfc[t];
#pragma unroll 8
        for (int ic = 0; ic < 64; ++ic)
            r += sPooled[ic] * __ldg(&Wfc[ic * 64 + t]);
        out[e * 64 + t] = r;
    }
}

// ---------------------------------------------------------------------------
extern "C" void kernel_launch(void* const* d_in, const int* in_sizes, int n_in,
                              void* d_out, int out_size)
{
    const float* data   = (const float*)d_in[0];
    const int*   clusts = (const int*)d_in[1];
    const void*  cmask  = d_in[2];
    const int*   eidx   = (const int*)d_in[3];
    const float* W1     = (const float*)d_in[4];
    const float* b1     = (const float*)d_in[5];
    const float* W2     = (const float*)d_in[6];
    const float* b2     = (const float*)d_in[7];
    const float* W3     = (const float*)d_in[8];
    const float* b3     = (const float*)d_in[9];
    const float* Wfc    = (const float*)d_in[10];
    const float* bfc    = (const float*)d_in[11];
    float*       out    = (float*)d_out;

    const int C = in_sizes[1] / NPT;   // 256
    const int E = in_sizes[3] / 2;     // 1024
    const int maskWords = in_sizes[2] / 4;

    cudaFuncSetAttribute(vox_acc_kernel,
        cudaFuncAttributeMaxDynamicSharedMemorySize, VOXA_SMEM);
    cudaFuncSetAttribute(conv2_mma_kernel,
        cudaFuncAttributeMaxDynamicSharedMemorySize, C2MM_SMEM);
    cudaFuncSetAttribute(conv3_mma_kernel,
        cudaFuncAttributeMaxDynamicSharedMemorySize, C3MM_SMEM);

    detect_kernel<<<1, 256>>>(eidx, (const unsigned int*)cmask, E, maskWords);
    wtrans_kernel<<<216, 256>>>(W2, W3);
    vox_tab_kernel<<<C, 256>>>(data, clusts, cmask);
    vox_acc_kernel<<<dim3(C, 4), 256, VOXA_SMEM>>>();
    conv1c_kernel<<<C * 4, 256>>>(W1);
    conv2_mma_kernel<<<E * 2, 256, C2MM_SMEM>>>(eidx, b1, b2, E, C);
    conv3_mma_kernel<<<E, 256, C3MM_SMEM>>>(b3, Wfc, bfc, out);
}